// round 1
// baseline (speedup 1.0000x reference)
#include <cuda_runtime.h>

// Problem constants
// feat: [32, 2048, 32, 32] f32   d_in[0]
// cam : [32, 2048, 32, 32] f32   d_in[1]
// Wq  : [128, 2048] f32          d_in[2]
// Wk  : [128, 2048] f32          d_in[3]
// alpha: [] f32                  d_in[4]
// out : [32, 2048, 32, 32] f32

#define BATCH 32
#define CCH   2048
#define HW    1024
#define MID   128

#define BM 128
#define BN 128
#define BK 8
#define PADF 4

// Scratch (allocation-free rule: __device__ globals)
static __device__ float g_W[2 * MID * CCH];                 // 2 MB  (Wq rows 0..127, Wk rows 128..255)
static __device__ float g_f12[(long)BATCH * 2 * MID * HW];  // 32 MB
static __device__ float g_P[(long)BATCH * HW * HW];         // 128 MB

// ---------------------------------------------------------------------------
// Generic fp32 SGEMM: C[M,N] = sum_k A(m,k) * B(n or k...)  per-batch (blockIdx.z)
//   A_K_CONTIG: A stored [M,K] row-major (K contiguous). else A stored [K,M] (M contiguous).
//   B_N_CONTIG: B stored [K,N] row-major (N contiguous). else B stored [N,K] (K contiguous).
//   EPI == 0: C = acc
//   EPI == 2: C = alpha*acc + A[m*K + n]   (requires K==N; used for out = alpha*cam@P^T + cam)
// ---------------------------------------------------------------------------
template<bool A_K_CONTIG, bool B_N_CONTIG, int EPI>
__global__ void __launch_bounds__(256, 2)
sgemm_kernel(const float* __restrict__ Ag, const float* __restrict__ Bg,
             float* __restrict__ Cg,
             int M, int N, int K,
             long sA, long sB, long sC,
             const float* __restrict__ alphap)
{
    const int b = blockIdx.z;
    const float* A = Ag + (long)b * sA;
    const float* B = Bg + (long)b * sB;
    float* C = Cg + (long)b * sC;

    __shared__ float As[2][BK][BM + PADF];
    __shared__ float Bs[2][BK][BN + PADF];

    const int tid = threadIdx.x;
    const int tx = tid & 15;        // 0..15  -> N direction
    const int ty = tid >> 4;        // 0..15  -> M direction
    const int mBlock = blockIdx.y * BM;
    const int nBlock = blockIdx.x * BN;

    float acc[2][2][4][4];
#pragma unroll
    for (int p = 0; p < 2; p++)
#pragma unroll
        for (int q = 0; q < 2; q++)
#pragma unroll
            for (int i = 0; i < 4; i++)
#pragma unroll
                for (int j = 0; j < 4; j++)
                    acc[p][q][i][j] = 0.f;

    auto loadA = [&](int k0, int buf) {
        if (A_K_CONTIG) {
            // A [M,K], lda = K. 2 threads per row, float4 along K.
            const int m  = tid >> 1;
            const int k4 = (tid & 1) * 4;
            float4 v = *reinterpret_cast<const float4*>(A + (long)(mBlock + m) * K + k0 + k4);
            As[buf][k4 + 0][m] = v.x;
            As[buf][k4 + 1][m] = v.y;
            As[buf][k4 + 2][m] = v.z;
            As[buf][k4 + 3][m] = v.w;
        } else {
            // A [K,M], lda = M. 32 threads per k-row, float4 along M.
            const int k  = tid >> 5;
            const int m4 = (tid & 31) * 4;
            float4 v = *reinterpret_cast<const float4*>(A + (long)(k0 + k) * M + mBlock + m4);
            *reinterpret_cast<float4*>(&As[buf][k][m4]) = v;
        }
    };
    auto loadB = [&](int k0, int buf) {
        if (B_N_CONTIG) {
            // B [K,N], ldb = N.
            const int k  = tid >> 5;
            const int n4 = (tid & 31) * 4;
            float4 v = *reinterpret_cast<const float4*>(B + (long)(k0 + k) * N + nBlock + n4);
            *reinterpret_cast<float4*>(&Bs[buf][k][n4]) = v;
        } else {
            // B [N,K], ldb = K.
            const int n  = tid >> 1;
            const int k4 = (tid & 1) * 4;
            float4 v = *reinterpret_cast<const float4*>(B + (long)(nBlock + n) * K + k0 + k4);
            Bs[buf][k4 + 0][n] = v.x;
            Bs[buf][k4 + 1][n] = v.y;
            Bs[buf][k4 + 2][n] = v.z;
            Bs[buf][k4 + 3][n] = v.w;
        }
    };

    loadA(0, 0);
    loadB(0, 0);
    __syncthreads();

    int buf = 0;
    for (int k0 = 0; k0 < K; k0 += BK) {
        const int nbuf = buf ^ 1;
        if (k0 + BK < K) {
            loadA(k0 + BK, nbuf);
            loadB(k0 + BK, nbuf);
        }
#pragma unroll
        for (int kk = 0; kk < BK; kk++) {
            float a[2][4], bb[2][4];
            *reinterpret_cast<float4*>(a[0])  = *reinterpret_cast<const float4*>(&As[buf][kk][ty * 4]);
            *reinterpret_cast<float4*>(a[1])  = *reinterpret_cast<const float4*>(&As[buf][kk][64 + ty * 4]);
            *reinterpret_cast<float4*>(bb[0]) = *reinterpret_cast<const float4*>(&Bs[buf][kk][tx * 4]);
            *reinterpret_cast<float4*>(bb[1]) = *reinterpret_cast<const float4*>(&Bs[buf][kk][64 + tx * 4]);
#pragma unroll
            for (int p = 0; p < 2; p++)
#pragma unroll
                for (int q = 0; q < 2; q++)
#pragma unroll
                    for (int i = 0; i < 4; i++)
#pragma unroll
                        for (int j = 0; j < 4; j++)
                            acc[p][q][i][j] += a[p][i] * bb[q][j];
        }
        __syncthreads();
        buf = nbuf;
    }

    float alpha_v = 1.0f;
    if (EPI == 2) alpha_v = *alphap;

#pragma unroll
    for (int p = 0; p < 2; p++)
#pragma unroll
        for (int i = 0; i < 4; i++) {
            const int m = mBlock + p * 64 + ty * 4 + i;
#pragma unroll
            for (int q = 0; q < 2; q++) {
                const int n = nBlock + q * 64 + tx * 4;
                float4 r;
                r.x = acc[p][q][i][0];
                r.y = acc[p][q][i][1];
                r.z = acc[p][q][i][2];
                r.w = acc[p][q][i][3];
                if (EPI == 2) {
                    float4 c4 = *reinterpret_cast<const float4*>(A + (long)m * K + n);
                    r.x = alpha_v * r.x + c4.x;
                    r.y = alpha_v * r.y + c4.y;
                    r.z = alpha_v * r.z + c4.z;
                    r.w = alpha_v * r.w + c4.w;
                }
                *reinterpret_cast<float4*>(C + (long)m * N + n) = r;
            }
        }
}

// ---------------------------------------------------------------------------
// In-place row softmax over rows of length 1024. One block (256 thr) per row.
// ---------------------------------------------------------------------------
__global__ void __launch_bounds__(256)
softmax_kernel(float* __restrict__ P)
{
    __shared__ float red_m[8];
    __shared__ float red_s[8];

    const long row = blockIdx.x;
    float4* p = reinterpret_cast<float4*>(P + row * (long)HW);
    float4 v = p[threadIdx.x];

    const int lane = threadIdx.x & 31;
    const int warp = threadIdx.x >> 5;

    // row max
    float m = fmaxf(fmaxf(v.x, v.y), fmaxf(v.z, v.w));
#pragma unroll
    for (int o = 16; o; o >>= 1) m = fmaxf(m, __shfl_xor_sync(0xffffffffu, m, o));
    if (lane == 0) red_m[warp] = m;
    __syncthreads();
    m = red_m[0];
#pragma unroll
    for (int i = 1; i < 8; i++) m = fmaxf(m, red_m[i]);

    // exp + row sum
    float4 e;
    e.x = expf(v.x - m);
    e.y = expf(v.y - m);
    e.z = expf(v.z - m);
    e.w = expf(v.w - m);
    float s = e.x + e.y + e.z + e.w;
#pragma unroll
    for (int o = 16; o; o >>= 1) s += __shfl_xor_sync(0xffffffffu, s, o);
    if (lane == 0) red_s[warp] = s;
    __syncthreads();
    s = red_s[0];
#pragma unroll
    for (int i = 1; i < 8; i++) s += red_s[i];

    const float inv = 1.0f / s;
    e.x *= inv; e.y *= inv; e.z *= inv; e.w *= inv;
    p[threadIdx.x] = e;
}

// ---------------------------------------------------------------------------
extern "C" void kernel_launch(void* const* d_in, const int* in_sizes, int n_in,
                              void* d_out, int out_size)
{
    const float* feat  = (const float*)d_in[0];
    const float* cam   = (const float*)d_in[1];
    const float* Wq    = (const float*)d_in[2];
    const float* Wk    = (const float*)d_in[3];
    const float* alpha = (const float*)d_in[4];
    float* out = (float*)d_out;

    float *w, *f12, *P;
    cudaGetSymbolAddress((void**)&w, g_W);
    cudaGetSymbolAddress((void**)&f12, g_f12);
    cudaGetSymbolAddress((void**)&P, g_P);

    // concat Wq / Wk into one [256, 2048] matrix
    cudaMemcpyAsync(w,               Wq, (size_t)MID * CCH * sizeof(float), cudaMemcpyDeviceToDevice);
    cudaMemcpyAsync(w + MID * CCH,   Wk, (size_t)MID * CCH * sizeof(float), cudaMemcpyDeviceToDevice);

    // GEMM1: f12[b, m, n] = W[m, k] * feat[b, k, n]   (M=256, N=1024, K=2048)
    {
        dim3 grid(HW / BN, (2 * MID) / BM, BATCH);
        sgemm_kernel<true, true, 0><<<grid, 256>>>(
            w, feat, f12,
            2 * MID, HW, CCH,
            0L, (long)CCH * HW, (long)2 * MID * HW,
            nullptr);
    }

    // GEMM2: S[b, i, j] = f1[b, m, i] * f2[b, m, j]   (M=N=1024, K=128)
    {
        dim3 grid(HW / BN, HW / BM, BATCH);
        sgemm_kernel<false, true, 0><<<grid, 256>>>(
            f12, f12 + (long)MID * HW, P,
            HW, HW, MID,
            (long)2 * MID * HW, (long)2 * MID * HW, (long)HW * HW,
            nullptr);
    }

    // Softmax over rows of P
    softmax_kernel<<<BATCH * HW, 256>>>(P);

    // GEMM3: out[b, c, i] = alpha * sum_j cam[b, c, j] * P[b, i, j] + cam[b, c, i]
    {
        dim3 grid(HW / BN, CCH / BM, BATCH);
        sgemm_kernel<true, false, 2><<<grid, 256>>>(
            cam, P, out,
            CCH, HW, HW,
            (long)CCH * HW, (long)HW * HW, (long)CCH * HW,
            alpha);
    }
}

// round 3
// speedup vs baseline: 1.8767x; 1.8767x over previous
#include <cuda_runtime.h>
#include <cstdint>

// Problem constants
// feat: [32, 2048, 32, 32] f32   d_in[0]
// cam : [32, 2048, 32, 32] f32   d_in[1]
// Wq  : [128, 2048] f32          d_in[2]
// Wk  : [128, 2048] f32          d_in[3]
// alpha: [] f32                  d_in[4]
// out : [32, 2048, 32, 32] f32

#define BATCH 32
#define CCH   2048
#define HW    1024
#define MID   128

// Scratch (allocation-free rule: __device__ globals)
static __device__ float g_W[2 * MID * CCH];                 // 2 MB
static __device__ float g_f12[(long)BATCH * 2 * MID * HW];  // 32 MB
static __device__ float g_P[(long)BATCH * HW * HW];         // 128 MB

__device__ __forceinline__ uint32_t smem_u32(const void* p) {
    uint32_t a;
    asm("{ .reg .u64 t; cvta.to.shared.u64 t, %1; cvt.u32.u64 %0, t; }" : "=r"(a) : "l"(p));
    return a;
}
__device__ __forceinline__ uint32_t f2tf32(float f) {
    uint32_t r;
    asm("cvt.rna.tf32.f32 %0, %1;" : "=r"(r) : "f"(f));
    return r;
}
__device__ __forceinline__ void mma_tf32(float* c, const uint32_t* a, const uint32_t* b) {
    asm volatile(
        "mma.sync.aligned.m16n8k8.row.col.f32.tf32.tf32.f32 "
        "{%0,%1,%2,%3}, {%4,%5,%6,%7}, {%8,%9}, {%0,%1,%2,%3};"
        : "+f"(c[0]), "+f"(c[1]), "+f"(c[2]), "+f"(c[3])
        : "r"(a[0]), "r"(a[1]), "r"(a[2]), "r"(a[3]), "r"(b[0]), "r"(b[1]));
}
#define CP_ASYNC16(smem_addr, gptr) \
    asm volatile("cp.async.cg.shared.global [%0], [%1], 16;" :: "r"(smem_addr), "l"(gptr))
#define CP_COMMIT() asm volatile("cp.async.commit_group;" ::: "memory")
#define CP_WAIT2()  asm volatile("cp.async.wait_group 2;"  ::: "memory")

// ===========================================================================
// GEMM3 (legacy tensor path, tf32 mma.sync):
//   out[b, m, n] = alpha * sum_j cam[b, m, j] * P[b, n, j] + cam[b, m, n]
//   A = cam (row-major M x K), B = P (col-major K x N, i.e. P rows are n, K contig)
// ===========================================================================
#define G3_BM 128
#define G3_BN 128
#define G3_BK 16
#define G3_STAGES 4
#define G3_PITCH 20   // 16 + 4 pad (floats): conflict-free & 16B-aligned chunks
#define G3_TILE_FLOATS (128 * G3_PITCH)
#define G3_KITER (HW / G3_BK)   // 64

__global__ void __launch_bounds__(256, 2)
gemm3_mma_kernel(const float* __restrict__ cam, const float* __restrict__ P,
                 float* __restrict__ out, const float* __restrict__ alphap)
{
    extern __shared__ float sm[];
    float* smA = sm;
    float* smB = sm + G3_STAGES * G3_TILE_FLOATS;

    const int tid  = threadIdx.x;
    const int wid  = tid >> 5;
    const int lane = tid & 31;
    const int g    = lane >> 2;    // group id 0..7
    const int t    = lane & 3;     // thread-in-group 0..3
    const int wm   = wid >> 1;     // 0..3  (m direction)
    const int wn   = wid & 1;      // 0..1  (n direction)

    const int b  = blockIdx.z;
    const int m0 = blockIdx.y * G3_BM;
    const int n0 = blockIdx.x * G3_BN;
    const float* camB = cam + (long)b * CCH * HW;
    const float* PB   = P   + (long)b * HW * HW;

    const uint32_t smA_u = smem_u32(smA);
    const uint32_t smB_u = smem_u32(smB);

    float acc[2][8][4];
#pragma unroll
    for (int i = 0; i < 2; i++)
#pragma unroll
        for (int j = 0; j < 8; j++)
#pragma unroll
            for (int k = 0; k < 4; k++) acc[i][j][k] = 0.f;

    auto load_stage = [&](int s, int k0) {
        const uint32_t sa = smA_u + (uint32_t)(s * G3_TILE_FLOATS) * 4u;
        const uint32_t sb = smB_u + (uint32_t)(s * G3_TILE_FLOATS) * 4u;
        // A: 128 rows x 16 floats = 512 x 16B chunks; 2 per thread
#pragma unroll
        for (int i = 0; i < 2; i++) {
            int c = tid + i * 256;
            int row = c >> 2, cc = c & 3;
            CP_ASYNC16(sa + (uint32_t)(row * G3_PITCH + cc * 4) * 4u,
                       camB + (long)(m0 + row) * HW + k0 + cc * 4);
        }
        // B: P rows (n), K contig
#pragma unroll
        for (int i = 0; i < 2; i++) {
            int c = tid + i * 256;
            int row = c >> 2, cc = c & 3;
            CP_ASYNC16(sb + (uint32_t)(row * G3_PITCH + cc * 4) * 4u,
                       PB + (long)(n0 + row) * HW + k0 + cc * 4);
        }
    };

    // Prologue: fill 3 of 4 stages
#pragma unroll
    for (int s = 0; s < G3_STAGES - 1; s++) {
        load_stage(s, s * G3_BK);
        CP_COMMIT();
    }

    for (int it = 0; it < G3_KITER; it++) {
        CP_WAIT2();
        __syncthreads();

        const int s = it & (G3_STAGES - 1);
        const float* sa = smA + s * G3_TILE_FLOATS;
        const float* sb = smB + s * G3_TILE_FLOATS;

#pragma unroll
        for (int step = 0; step < 2; step++) {
            const int kk = step * 8;
            uint32_t a[2][4];
#pragma unroll
            for (int mt = 0; mt < 2; mt++) {
                const int r0 = wm * 32 + mt * 16 + g;
                a[mt][0] = f2tf32(sa[r0 * G3_PITCH + kk + t]);
                a[mt][1] = f2tf32(sa[(r0 + 8) * G3_PITCH + kk + t]);
                a[mt][2] = f2tf32(sa[r0 * G3_PITCH + kk + t + 4]);
                a[mt][3] = f2tf32(sa[(r0 + 8) * G3_PITCH + kk + t + 4]);
            }
            uint32_t bb[8][2];
#pragma unroll
            for (int nt = 0; nt < 8; nt++) {
                const int n = wn * 64 + nt * 8 + g;
                bb[nt][0] = f2tf32(sb[n * G3_PITCH + kk + t]);
                bb[nt][1] = f2tf32(sb[n * G3_PITCH + kk + t + 4]);
            }
#pragma unroll
            for (int mt = 0; mt < 2; mt++)
#pragma unroll
                for (int nt = 0; nt < 8; nt++)
                    mma_tf32(acc[mt][nt], a[mt], bb[nt]);
        }

        __syncthreads();
        if (it + G3_STAGES - 1 < G3_KITER)
            load_stage((it + G3_STAGES - 1) & (G3_STAGES - 1), (it + G3_STAGES - 1) * G3_BK);
        CP_COMMIT();
    }

    // Epilogue: out = alpha*acc + cam (C frag cols 2t, 2t+1 are contiguous -> float2)
    const float alpha = *alphap;
    float* outB = out + (long)b * CCH * HW;
#pragma unroll
    for (int mt = 0; mt < 2; mt++) {
        const int mrow = m0 + wm * 32 + mt * 16 + g;
#pragma unroll
        for (int nt = 0; nt < 8; nt++) {
            const int n = n0 + wn * 64 + nt * 8 + 2 * t;
            {
                const float2 cv = *(const float2*)(camB + (long)mrow * HW + n);
                float2 o;
                o.x = alpha * acc[mt][nt][0] + cv.x;
                o.y = alpha * acc[mt][nt][1] + cv.y;
                *(float2*)(outB + (long)mrow * HW + n) = o;
            }
            {
                const float2 cv = *(const float2*)(camB + (long)(mrow + 8) * HW + n);
                float2 o;
                o.x = alpha * acc[mt][nt][2] + cv.x;
                o.y = alpha * acc[mt][nt][3] + cv.y;
                *(float2*)(outB + (long)(mrow + 8) * HW + n) = o;
            }
        }
    }
}

#define G3_SMEM_BYTES (2 * G3_STAGES * G3_TILE_FLOATS * 4)  // 81920

// ===========================================================================
// fp32 SIMT SGEMM (GEMM1/GEMM2 — precision-critical pre-softmax path)
// ===========================================================================
#define BM 128
#define BN 128
#define BK 8
#define PADF 4

template<bool A_K_CONTIG, bool B_N_CONTIG>
__global__ void __launch_bounds__(256, 2)
sgemm_kernel(const float* __restrict__ Ag, const float* __restrict__ Bg,
             float* __restrict__ Cg,
             int M, int N, int K,
             long sA, long sB, long sC)
{
    const int b = blockIdx.z;
    const float* A = Ag + (long)b * sA;
    const float* B = Bg + (long)b * sB;
    float* C = Cg + (long)b * sC;

    __shared__ float As[2][BK][BM + PADF];
    __shared__ float Bs[2][BK][BN + PADF];

    const int tid = threadIdx.x;
    const int tx = tid & 15;
    const int ty = tid >> 4;
    const int mBlock = blockIdx.y * BM;
    const int nBlock = blockIdx.x * BN;

    float acc[2][2][4][4];
#pragma unroll
    for (int p = 0; p < 2; p++)
#pragma unroll
        for (int q = 0; q < 2; q++)
#pragma unroll
            for (int i = 0; i < 4; i++)
#pragma unroll
                for (int j = 0; j < 4; j++)
                    acc[p][q][i][j] = 0.f;

    auto loadA = [&](int k0, int buf) {
        if (A_K_CONTIG) {
            const int m  = tid >> 1;
            const int k4 = (tid & 1) * 4;
            float4 v = *reinterpret_cast<const float4*>(A + (long)(mBlock + m) * K + k0 + k4);
            As[buf][k4 + 0][m] = v.x;
            As[buf][k4 + 1][m] = v.y;
            As[buf][k4 + 2][m] = v.z;
            As[buf][k4 + 3][m] = v.w;
        } else {
            const int k  = tid >> 5;
            const int m4 = (tid & 31) * 4;
            float4 v = *reinterpret_cast<const float4*>(A + (long)(k0 + k) * M + mBlock + m4);
            *reinterpret_cast<float4*>(&As[buf][k][m4]) = v;
        }
    };
    auto loadB = [&](int k0, int buf) {
        if (B_N_CONTIG) {
            const int k  = tid >> 5;
            const int n4 = (tid & 31) * 4;
            float4 v = *reinterpret_cast<const float4*>(B + (long)(k0 + k) * N + nBlock + n4);
            *reinterpret_cast<float4*>(&Bs[buf][k][n4]) = v;
        } else {
            const int n  = tid >> 1;
            const int k4 = (tid & 1) * 4;
            float4 v = *reinterpret_cast<const float4*>(B + (long)(nBlock + n) * K + k0 + k4);
            Bs[buf][k4 + 0][n] = v.x;
            Bs[buf][k4 + 1][n] = v.y;
            Bs[buf][k4 + 2][n] = v.z;
            Bs[buf][k4 + 3][n] = v.w;
        }
    };

    loadA(0, 0);
    loadB(0, 0);
    __syncthreads();

    int buf = 0;
    for (int k0 = 0; k0 < K; k0 += BK) {
        const int nbuf = buf ^ 1;
        if (k0 + BK < K) {
            loadA(k0 + BK, nbuf);
            loadB(k0 + BK, nbuf);
        }
#pragma unroll
        for (int kk = 0; kk < BK; kk++) {
            float a[2][4], bb[2][4];
            *reinterpret_cast<float4*>(a[0])  = *reinterpret_cast<const float4*>(&As[buf][kk][ty * 4]);
            *reinterpret_cast<float4*>(a[1])  = *reinterpret_cast<const float4*>(&As[buf][kk][64 + ty * 4]);
            *reinterpret_cast<float4*>(bb[0]) = *reinterpret_cast<const float4*>(&Bs[buf][kk][tx * 4]);
            *reinterpret_cast<float4*>(bb[1]) = *reinterpret_cast<const float4*>(&Bs[buf][kk][64 + tx * 4]);
#pragma unroll
            for (int p = 0; p < 2; p++)
#pragma unroll
                for (int q = 0; q < 2; q++)
#pragma unroll
                    for (int i = 0; i < 4; i++)
#pragma unroll
                        for (int j = 0; j < 4; j++)
                            acc[p][q][i][j] += a[p][i] * bb[q][j];
        }
        __syncthreads();
        buf = nbuf;
    }

#pragma unroll
    for (int p = 0; p < 2; p++)
#pragma unroll
        for (int i = 0; i < 4; i++) {
            const int m = mBlock + p * 64 + ty * 4 + i;
#pragma unroll
            for (int q = 0; q < 2; q++) {
                const int n = nBlock + q * 64 + tx * 4;
                float4 r;
                r.x = acc[p][q][i][0];
                r.y = acc[p][q][i][1];
                r.z = acc[p][q][i][2];
                r.w = acc[p][q][i][3];
                *reinterpret_cast<float4*>(C + (long)m * N + n) = r;
            }
        }
}

// ---------------------------------------------------------------------------
// In-place row softmax over rows of length 1024. One block (256 thr) per row.
// ---------------------------------------------------------------------------
__global__ void __launch_bounds__(256)
softmax_kernel(float* __restrict__ P)
{
    __shared__ float red_m[8];
    __shared__ float red_s[8];

    const long row = blockIdx.x;
    float4* p = reinterpret_cast<float4*>(P + row * (long)HW);
    float4 v = p[threadIdx.x];

    const int lane = threadIdx.x & 31;
    const int warp = threadIdx.x >> 5;

    float m = fmaxf(fmaxf(v.x, v.y), fmaxf(v.z, v.w));
#pragma unroll
    for (int o = 16; o; o >>= 1) m = fmaxf(m, __shfl_xor_sync(0xffffffffu, m, o));
    if (lane == 0) red_m[warp] = m;
    __syncthreads();
    m = red_m[0];
#pragma unroll
    for (int i = 1; i < 8; i++) m = fmaxf(m, red_m[i]);

    float4 e;
    e.x = expf(v.x - m);
    e.y = expf(v.y - m);
    e.z = expf(v.z - m);
    e.w = expf(v.w - m);
    float s = e.x + e.y + e.z + e.w;
#pragma unroll
    for (int o = 16; o; o >>= 1) s += __shfl_xor_sync(0xffffffffu, s, o);
    if (lane == 0) red_s[warp] = s;
    __syncthreads();
    s = red_s[0];
#pragma unroll
    for (int i = 1; i < 8; i++) s += red_s[i];

    const float inv = 1.0f / s;
    e.x *= inv; e.y *= inv; e.z *= inv; e.w *= inv;
    p[threadIdx.x] = e;
}

// ---------------------------------------------------------------------------
extern "C" void kernel_launch(void* const* d_in, const int* in_sizes, int n_in,
                              void* d_out, int out_size)
{
    const float* feat  = (const float*)d_in[0];
    const float* cam   = (const float*)d_in[1];
    const float* Wq    = (const float*)d_in[2];
    const float* Wk    = (const float*)d_in[3];
    const float* alpha = (const float*)d_in[4];
    float* out = (float*)d_out;

    float *w, *f12, *P;
    cudaGetSymbolAddress((void**)&w, g_W);
    cudaGetSymbolAddress((void**)&f12, g_f12);
    cudaGetSymbolAddress((void**)&P, g_P);

    // concat Wq / Wk into one [256, 2048] matrix
    cudaMemcpyAsync(w,             Wq, (size_t)MID * CCH * sizeof(float), cudaMemcpyDeviceToDevice);
    cudaMemcpyAsync(w + MID * CCH, Wk, (size_t)MID * CCH * sizeof(float), cudaMemcpyDeviceToDevice);

    // GEMM1: f12[b, m, n] = W[m, k] * feat[b, k, n]   (M=256, N=1024, K=2048), fp32
    {
        dim3 grid(HW / BN, (2 * MID) / BM, BATCH);
        sgemm_kernel<true, true><<<grid, 256>>>(
            w, feat, f12,
            2 * MID, HW, CCH,
            0L, (long)CCH * HW, (long)2 * MID * HW);
    }

    // GEMM2: S[b, i, j] = f1[b, m, i] * f2[b, m, j]   (M=N=1024, K=128), fp32
    {
        dim3 grid(HW / BN, HW / BM, BATCH);
        sgemm_kernel<false, true><<<grid, 256>>>(
            f12, f12 + (long)MID * HW, P,
            HW, HW, MID,
            (long)2 * MID * HW, (long)2 * MID * HW, (long)HW * HW);
    }

    // Softmax over rows of P
    softmax_kernel<<<BATCH * HW, 256>>>(P);

    // GEMM3 on legacy tensor path (tf32 mma.sync): out = alpha * cam @ P^T + cam
    {
        cudaFuncSetAttribute(gemm3_mma_kernel,
                             cudaFuncAttributeMaxDynamicSharedMemorySize, G3_SMEM_BYTES);
        dim3 grid(HW / G3_BN, CCH / G3_BM, BATCH);
        gemm3_mma_kernel<<<grid, 256, G3_SMEM_BYTES>>>(cam, P, out, alpha);
    }
}

// round 4
// speedup vs baseline: 2.2245x; 1.1853x over previous
#include <cuda_runtime.h>
#include <cstdint>

// Problem constants
// feat: [32, 2048, 32, 32] f32   d_in[0]
// cam : [32, 2048, 32, 32] f32   d_in[1]
// Wq  : [128, 2048] f32          d_in[2]
// Wk  : [128, 2048] f32          d_in[3]
// alpha: [] f32                  d_in[4]
// out : [32, 2048, 32, 32] f32

#define BATCH 32
#define CCH   2048
#define HW    1024
#define MID   128

// Scratch (allocation-free rule: __device__ globals)
static __device__ float g_W[2 * MID * CCH];                  // 2 MB
static __device__ float g_f12[(long)BATCH * 2 * MID * HW];   // 32 MB
static __device__ float g_P[(long)BATCH * HW * HW];          // 128 MB (permuted tf32 after softmax)
static __device__ float g_camT[(long)BATCH * CCH * HW];      // 256 MB (permuted tf32 copy of cam)

// ===========================================================================
// Helpers
// ===========================================================================
__device__ __forceinline__ uint32_t smem_u32(const void* p) {
    uint32_t a;
    asm("{ .reg .u64 t; cvta.to.shared.u64 t, %1; cvt.u32.u64 %0, t; }" : "=r"(a) : "l"(p));
    return a;
}
__device__ __forceinline__ uint32_t f2tf32(float f) {
    uint32_t r;
    asm("cvt.rna.tf32.f32 %0, %1;" : "=r"(r) : "f"(f));
    return r;
}
__device__ __forceinline__ void mma_tf32(float* c, const uint32_t* a, const uint32_t* b) {
    asm volatile(
        "mma.sync.aligned.m16n8k8.row.col.f32.tf32.tf32.f32 "
        "{%0,%1,%2,%3}, {%4,%5,%6,%7}, {%8,%9}, {%0,%1,%2,%3};"
        : "+f"(c[0]), "+f"(c[1]), "+f"(c[2]), "+f"(c[3])
        : "r"(a[0]), "r"(a[1]), "r"(a[2]), "r"(a[3]), "r"(b[0]), "r"(b[1]));
}
#define CP_ASYNC16(smem_addr, gptr) \
    asm volatile("cp.async.cg.shared.global [%0], [%1], 16;" :: "r"(smem_addr), "l"(gptr))
#define CP_COMMIT() asm volatile("cp.async.commit_group;" ::: "memory")
#define CP_WAIT2()  asm volatile("cp.async.wait_group 2;"  ::: "memory")

// Fragment permutation within each 16-float k-chunk: original k = s*4+t stored
// at position t*4+s. A float4 load at offset 4t then yields k = {t, t+4, t+8, t+12},
// exactly the (kk=0, kk=8) fragment columns of two m16n8k8 steps.

// ===========================================================================
// prep_cam: camT = permuted tf32-rounded copy of cam
// ===========================================================================
__global__ void __launch_bounds__(256)
prep_cam_kernel(const float* __restrict__ cam, float* __restrict__ camT)
{
    const long i4 = (long)blockIdx.x * blockDim.x + threadIdx.x;  // float4 index
    const float4 v = reinterpret_cast<const float4*>(cam)[i4];
    float* dst = camT + (i4 >> 2) * 16 + (int)(i4 & 3);
    dst[0]  = __uint_as_float(f2tf32(v.x));
    dst[4]  = __uint_as_float(f2tf32(v.y));
    dst[8]  = __uint_as_float(f2tf32(v.z));
    dst[12] = __uint_as_float(f2tf32(v.w));
}

// ===========================================================================
// Softmax: in-place over rows of 1024, output written PERMUTED + tf32-rounded.
// One block (256 thr) per row. Reads precede first __syncthreads; writes follow
// the last one, so the in-place permutation is race-free.
// ===========================================================================
__global__ void __launch_bounds__(256)
softmax_kernel(float* __restrict__ P)
{
    __shared__ float red_m[8];
    __shared__ float red_s[8];

    const long row = blockIdx.x;
    float* rowp = P + row * (long)HW;
    const float4 v = reinterpret_cast<const float4*>(rowp)[threadIdx.x];

    const int lane = threadIdx.x & 31;
    const int warp = threadIdx.x >> 5;

    float m = fmaxf(fmaxf(v.x, v.y), fmaxf(v.z, v.w));
#pragma unroll
    for (int o = 16; o; o >>= 1) m = fmaxf(m, __shfl_xor_sync(0xffffffffu, m, o));
    if (lane == 0) red_m[warp] = m;
    __syncthreads();
    m = red_m[0];
#pragma unroll
    for (int i = 1; i < 8; i++) m = fmaxf(m, red_m[i]);

    float4 e;
    e.x = expf(v.x - m);
    e.y = expf(v.y - m);
    e.z = expf(v.z - m);
    e.w = expf(v.w - m);
    float s = e.x + e.y + e.z + e.w;
#pragma unroll
    for (int o = 16; o; o >>= 1) s += __shfl_xor_sync(0xffffffffu, s, o);
    if (lane == 0) red_s[warp] = s;
    __syncthreads();
    s = red_s[0];
#pragma unroll
    for (int i = 1; i < 8; i++) s += red_s[i];

    const float inv = 1.0f / s;
    float* dst = rowp + (threadIdx.x >> 2) * 16 + (threadIdx.x & 3);
    dst[0]  = __uint_as_float(f2tf32(e.x * inv));
    dst[4]  = __uint_as_float(f2tf32(e.y * inv));
    dst[8]  = __uint_as_float(f2tf32(e.z * inv));
    dst[12] = __uint_as_float(f2tf32(e.w * inv));
}

// ===========================================================================
// GEMM3 (tf32 mma.sync, vectorized fragments, zero cvt):
//   out[b, m, n] = alpha * sum_j camT[b, m, j] * P[b, n, j] + cam[b, m, n]
//   Both operands pre-rounded tf32 + fragment-permuted in gmem.
// ===========================================================================
#define G3_BM 128
#define G3_BN 128
#define G3_BK 16
#define G3_STAGES 4
#define G3_PITCH 16                        // no pad: lds.128 pattern is conflict-free
#define G3_TILEF (128 * G3_PITCH)          // floats per tile
#define G3_STAGEF (2 * G3_TILEF)
#define G3_SMEM_BYTES (G3_STAGES * G3_STAGEF * 4)  // 65536
#define G3_KITER (HW / G3_BK)              // 64

__global__ void __launch_bounds__(256, 2)
gemm3_mma_kernel(const float* __restrict__ camT, const float* __restrict__ cam,
                 const float* __restrict__ P,
                 float* __restrict__ out, const float* __restrict__ alphap)
{
    extern __shared__ float sm[];

    const int tid  = threadIdx.x;
    const int wid  = tid >> 5;
    const int lane = tid & 31;
    const int g    = lane >> 2;
    const int t    = lane & 3;
    const int wm   = wid >> 1;     // 0..3
    const int wn   = wid & 1;      // 0..1

    const int b  = blockIdx.z;
    const int m0 = blockIdx.y * G3_BM;
    const int n0 = blockIdx.x * G3_BN;
    const float* camTB = camT + (long)b * CCH * HW;
    const float* camB  = cam  + (long)b * CCH * HW;
    const float* PB    = P    + (long)b * HW * HW;

    const uint32_t sm_u = smem_u32(sm);

    float acc[2][8][4];
#pragma unroll
    for (int i = 0; i < 2; i++)
#pragma unroll
        for (int j = 0; j < 8; j++)
#pragma unroll
            for (int k = 0; k < 4; k++) acc[i][j][k] = 0.f;

    auto load_stage = [&](int s, int k0) {
        const uint32_t sa = sm_u + (uint32_t)(s * G3_STAGEF) * 4u;
        const uint32_t sb = sa + (uint32_t)G3_TILEF * 4u;
        // A: 128 rows x 16 floats = 512 chunks of 16B; 2 per thread
#pragma unroll
        for (int i = 0; i < 2; i++) {
            int c = tid + i * 256;
            int row = c >> 2, cc = c & 3;
            CP_ASYNC16(sa + (uint32_t)(row * G3_PITCH + cc * 4) * 4u,
                       camTB + (long)(m0 + row) * HW + k0 + cc * 4);
        }
#pragma unroll
        for (int i = 0; i < 2; i++) {
            int c = tid + i * 256;
            int row = c >> 2, cc = c & 3;
            CP_ASYNC16(sb + (uint32_t)(row * G3_PITCH + cc * 4) * 4u,
                       PB + (long)(n0 + row) * HW + k0 + cc * 4);
        }
    };

#pragma unroll
    for (int s = 0; s < G3_STAGES - 1; s++) {
        load_stage(s, s * G3_BK);
        CP_COMMIT();
    }

    for (int it = 0; it < G3_KITER; it++) {
        CP_WAIT2();
        __syncthreads();

        const int s = it & (G3_STAGES - 1);
        const float* sa = sm + s * G3_STAGEF;
        const float* sb = sa + G3_TILEF;

        // A fragments: per mt, rows G and G+8; float4 covers both k-steps.
        float4 av[2][2];
#pragma unroll
        for (int mt = 0; mt < 2; mt++) {
            const int r0 = wm * 32 + mt * 16 + g;
            av[mt][0] = *reinterpret_cast<const float4*>(sa + r0 * G3_PITCH + t * 4);
            av[mt][1] = *reinterpret_cast<const float4*>(sa + (r0 + 8) * G3_PITCH + t * 4);
        }
        float4 bv[8];
#pragma unroll
        for (int nt = 0; nt < 8; nt++) {
            const int n = wn * 64 + nt * 8 + g;
            bv[nt] = *reinterpret_cast<const float4*>(sb + n * G3_PITCH + t * 4);
        }

#pragma unroll
        for (int mt = 0; mt < 2; mt++) {
            uint32_t a0[4] = { __float_as_uint(av[mt][0].x), __float_as_uint(av[mt][1].x),
                               __float_as_uint(av[mt][0].y), __float_as_uint(av[mt][1].y) };
            uint32_t a1[4] = { __float_as_uint(av[mt][0].z), __float_as_uint(av[mt][1].z),
                               __float_as_uint(av[mt][0].w), __float_as_uint(av[mt][1].w) };
#pragma unroll
            for (int nt = 0; nt < 8; nt++) {
                uint32_t b0[2] = { __float_as_uint(bv[nt].x), __float_as_uint(bv[nt].y) };
                uint32_t b1[2] = { __float_as_uint(bv[nt].z), __float_as_uint(bv[nt].w) };
                mma_tf32(acc[mt][nt], a0, b0);
                mma_tf32(acc[mt][nt], a1, b1);
            }
        }

        __syncthreads();
        if (it + G3_STAGES - 1 < G3_KITER)
            load_stage((it + G3_STAGES - 1) & (G3_STAGES - 1), (it + G3_STAGES - 1) * G3_BK);
        CP_COMMIT();
    }

    const float alpha = *alphap;
    float* outB = out + (long)b * CCH * HW;
#pragma unroll
    for (int mt = 0; mt < 2; mt++) {
        const int mrow = m0 + wm * 32 + mt * 16 + g;
#pragma unroll
        for (int nt = 0; nt < 8; nt++) {
            const int n = n0 + wn * 64 + nt * 8 + 2 * t;
            {
                const float2 cv = *(const float2*)(camB + (long)mrow * HW + n);
                float2 o;
                o.x = alpha * acc[mt][nt][0] + cv.x;
                o.y = alpha * acc[mt][nt][1] + cv.y;
                *(float2*)(outB + (long)mrow * HW + n) = o;
            }
            {
                const float2 cv = *(const float2*)(camB + (long)(mrow + 8) * HW + n);
                float2 o;
                o.x = alpha * acc[mt][nt][2] + cv.x;
                o.y = alpha * acc[mt][nt][3] + cv.y;
                *(float2*)(outB + (long)(mrow + 8) * HW + n) = o;
            }
        }
    }
}

// ===========================================================================
// GEMM1 / GEMM2 on tensor cores with 3xtf32 split (fp32-grade accuracy).
//   C[b, m, n] = sum_k A(m,k) * B(k,n)
//   AKC=true : A stored [M][K] (K contig)   — GEMM1 (A = W)
//   AKC=false: A stored [K][M] (M contig)   — GEMM2 (A = f1, rows are k)
//   B stored [K][N] (N contig) in both.
// ===========================================================================
#define T_BM 128
#define T_BN 128
#define T_BK 16
#define T_STAGES 4
#define PA_K 20       // pitch for A [BM][BK] (k-contig rows)
#define PA_M 136      // pitch for A [BK][BM] (m-contig rows); 136 % 32 == 8 -> conflict-free
#define PB_  136      // pitch for B [BK][BN]
#define T_ATILEF_K (T_BM * PA_K)   // 2560
#define T_ATILEF_M (T_BK * PA_M)   // 2176
#define T_BTILEF   (T_BK * PB_)    // 2176
#define T_ATILEF_MAX T_ATILEF_K
#define T_STAGEF (T_ATILEF_MAX + T_BTILEF)          // 4736
#define T_SMEM_BYTES (T_STAGES * T_STAGEF * 4)      // 75776

template<bool AKC>
__global__ void __launch_bounds__(256, 2)
mma3_gemm_kernel(const float* __restrict__ Ag, const float* __restrict__ Bg,
                 float* __restrict__ Cg,
                 int M, int N, int K,
                 long sA, long sB, long sC)
{
    extern __shared__ float sm[];

    const int tid  = threadIdx.x;
    const int wid  = tid >> 5;
    const int lane = tid & 31;
    const int g    = lane >> 2;
    const int t    = lane & 3;
    const int wm   = wid >> 1;
    const int wn   = wid & 1;

    const int b  = blockIdx.z;
    const int m0 = blockIdx.y * T_BM;
    const int n0 = blockIdx.x * T_BN;
    const float* A = Ag + (long)b * sA;
    const float* B = Bg + (long)b * sB;
    float* C = Cg + (long)b * sC;

    const uint32_t sm_u = smem_u32(sm);
    const int kIter = K / T_BK;

    float acc[2][8][4];
#pragma unroll
    for (int i = 0; i < 2; i++)
#pragma unroll
        for (int j = 0; j < 8; j++)
#pragma unroll
            for (int k = 0; k < 4; k++) acc[i][j][k] = 0.f;

    auto load_stage = [&](int s, int k0) {
        const uint32_t sa = sm_u + (uint32_t)(s * T_STAGEF) * 4u;
        const uint32_t sb = sa + (uint32_t)T_ATILEF_MAX * 4u;
        if (AKC) {
            // A [M][K]: 128 rows x 16 floats
#pragma unroll
            for (int i = 0; i < 2; i++) {
                int c = tid + i * 256;
                int row = c >> 2, cc = c & 3;
                CP_ASYNC16(sa + (uint32_t)(row * PA_K + cc * 4) * 4u,
                           A + (long)(m0 + row) * K + k0 + cc * 4);
            }
        } else {
            // A [K][M]: 16 k-rows x 128 floats
#pragma unroll
            for (int i = 0; i < 2; i++) {
                int c = tid + i * 256;
                int k = c >> 5, cc = c & 31;
                CP_ASYNC16(sa + (uint32_t)(k * PA_M + cc * 4) * 4u,
                           A + (long)(k0 + k) * M + m0 + cc * 4);
            }
        }
        // B [K][N]: 16 k-rows x 128 floats
#pragma unroll
        for (int i = 0; i < 2; i++) {
            int c = tid + i * 256;
            int k = c >> 5, cc = c & 31;
            CP_ASYNC16(sb + (uint32_t)(k * PB_ + cc * 4) * 4u,
                       B + (long)(k0 + k) * N + n0 + cc * 4);
        }
    };

#pragma unroll
    for (int s = 0; s < T_STAGES - 1; s++) {
        load_stage(s, s * T_BK);
        CP_COMMIT();
    }

    for (int it = 0; it < kIter; it++) {
        CP_WAIT2();
        __syncthreads();

        const int s = it & (T_STAGES - 1);
        const float* sa = sm + s * T_STAGEF;
        const float* sb = sa + T_ATILEF_MAX;

#pragma unroll
        for (int step = 0; step < 2; step++) {
            const int kk = step * 8;
            uint32_t ahi[2][4], alo[2][4];
#pragma unroll
            for (int mt = 0; mt < 2; mt++) {
                const int r0 = wm * 32 + mt * 16 + g;
                float x[4];
                if (AKC) {
                    x[0] = sa[r0 * PA_K + kk + t];
                    x[1] = sa[(r0 + 8) * PA_K + kk + t];
                    x[2] = sa[r0 * PA_K + kk + t + 4];
                    x[3] = sa[(r0 + 8) * PA_K + kk + t + 4];
                } else {
                    x[0] = sa[(kk + t) * PA_M + r0];
                    x[1] = sa[(kk + t) * PA_M + r0 + 8];
                    x[2] = sa[(kk + t + 4) * PA_M + r0];
                    x[3] = sa[(kk + t + 4) * PA_M + r0 + 8];
                }
#pragma unroll
                for (int q = 0; q < 4; q++) {
                    ahi[mt][q] = f2tf32(x[q]);
                    alo[mt][q] = f2tf32(x[q] - __uint_as_float(ahi[mt][q]));
                }
            }
#pragma unroll
            for (int nt = 0; nt < 8; nt++) {
                const int n = wn * 64 + nt * 8 + g;
                const float y0 = sb[(kk + t) * PB_ + n];
                const float y1 = sb[(kk + t + 4) * PB_ + n];
                uint32_t bhi[2], blo[2];
                bhi[0] = f2tf32(y0); blo[0] = f2tf32(y0 - __uint_as_float(bhi[0]));
                bhi[1] = f2tf32(y1); blo[1] = f2tf32(y1 - __uint_as_float(bhi[1]));
#pragma unroll
                for (int mt = 0; mt < 2; mt++) {
                    mma_tf32(acc[mt][nt], ahi[mt], bhi);
                    mma_tf32(acc[mt][nt], ahi[mt], blo);
                    mma_tf32(acc[mt][nt], alo[mt], bhi);
                }
            }
        }

        __syncthreads();
        if (it + T_STAGES - 1 < kIter)
            load_stage((it + T_STAGES - 1) & (T_STAGES - 1), (it + T_STAGES - 1) * T_BK);
        CP_COMMIT();
    }

#pragma unroll
    for (int mt = 0; mt < 2; mt++) {
        const int mrow = m0 + wm * 32 + mt * 16 + g;
#pragma unroll
        for (int nt = 0; nt < 8; nt++) {
            const int n = n0 + wn * 64 + nt * 8 + 2 * t;
            *(float2*)(C + (long)mrow * N + n) = make_float2(acc[mt][nt][0], acc[mt][nt][1]);
            *(float2*)(C + (long)(mrow + 8) * N + n) = make_float2(acc[mt][nt][2], acc[mt][nt][3]);
        }
    }
}

// ---------------------------------------------------------------------------
extern "C" void kernel_launch(void* const* d_in, const int* in_sizes, int n_in,
                              void* d_out, int out_size)
{
    const float* feat  = (const float*)d_in[0];
    const float* cam   = (const float*)d_in[1];
    const float* Wq    = (const float*)d_in[2];
    const float* Wk    = (const float*)d_in[3];
    const float* alpha = (const float*)d_in[4];
    float* out = (float*)d_out;

    float *w, *f12, *P, *camT;
    cudaGetSymbolAddress((void**)&w, g_W);
    cudaGetSymbolAddress((void**)&f12, g_f12);
    cudaGetSymbolAddress((void**)&P, g_P);
    cudaGetSymbolAddress((void**)&camT, g_camT);

    // concat Wq / Wk into one [256, 2048] matrix
    cudaMemcpyAsync(w,             Wq, (size_t)MID * CCH * sizeof(float), cudaMemcpyDeviceToDevice);
    cudaMemcpyAsync(w + MID * CCH, Wk, (size_t)MID * CCH * sizeof(float), cudaMemcpyDeviceToDevice);

    // prep: permuted tf32 copy of cam for GEMM3 A-operand
    {
        long n4 = (long)BATCH * CCH * HW / 4;
        prep_cam_kernel<<<(unsigned)(n4 / 256), 256>>>(cam, camT);
    }

    // GEMM1 (3xtf32): f12[b, m, n] = W[m, k] * feat[b, k, n]   (M=256, N=1024, K=2048)
    {
        cudaFuncSetAttribute(mma3_gemm_kernel<true>,
                             cudaFuncAttributeMaxDynamicSharedMemorySize, T_SMEM_BYTES);
        dim3 grid(HW / T_BN, (2 * MID) / T_BM, BATCH);
        mma3_gemm_kernel<true><<<grid, 256, T_SMEM_BYTES>>>(
            w, feat, f12,
            2 * MID, HW, CCH,
            0L, (long)CCH * HW, (long)2 * MID * HW);
    }

    // GEMM2 (3xtf32): S[b, i, j] = sum_m f1[b, m, i] * f2[b, m, j]  (M=N=1024, K=128)
    {
        cudaFuncSetAttribute(mma3_gemm_kernel<false>,
                             cudaFuncAttributeMaxDynamicSharedMemorySize, T_SMEM_BYTES);
        dim3 grid(HW / T_BN, HW / T_BM, BATCH);
        mma3_gemm_kernel<false><<<grid, 256, T_SMEM_BYTES>>>(
            f12, f12 + (long)MID * HW, P,
            HW, HW, MID,
            (long)2 * MID * HW, (long)2 * MID * HW, (long)HW * HW);
    }

    // Softmax (writes P permuted + tf32-rounded, ready for GEMM3 fragments)
    softmax_kernel<<<BATCH * HW, 256>>>(P);

    // GEMM3 (tf32 mma, vectorized fragments): out = alpha * cam @ P^T + cam
    {
        cudaFuncSetAttribute(gemm3_mma_kernel,
                             cudaFuncAttributeMaxDynamicSharedMemorySize, G3_SMEM_BYTES);
        dim3 grid(HW / G3_BN, CCH / G3_BM, BATCH);
        gemm3_mma_kernel<<<grid, 256, G3_SMEM_BYTES>>>(camT, cam, P, out, alpha);
    }
}

// round 5
// speedup vs baseline: 2.7524x; 1.2373x over previous
#include <cuda_runtime.h>
#include <cuda_fp16.h>
#include <cstdint>

// Problem constants
// feat: [32, 2048, 32, 32] f32   d_in[0]
// cam : [32, 2048, 32, 32] f32   d_in[1]
// Wq  : [128, 2048] f32          d_in[2]
// Wk  : [128, 2048] f32          d_in[3]
// alpha: [] f32                  d_in[4]
// out : [32, 2048, 32, 32] f32

#define BATCH 32
#define CCH   2048
#define HW    1024
#define MID   128

// Scratch (allocation-free rule: __device__ globals)
static __device__ float  g_W[2 * MID * CCH];                  // 2 MB
static __device__ float  g_f12[(long)BATCH * 2 * MID * HW];   // 32 MB
static __device__ float  g_P[(long)BATCH * HW * HW];          // 128 MB (fp32 logits; fp16 permuted after softmax, in-place)
static __device__ __half g_camH[(long)BATCH * CCH * HW];      // 128 MB (permuted fp16 copy of cam)

// ===========================================================================
// Helpers
// ===========================================================================
__device__ __forceinline__ uint32_t smem_u32(const void* p) {
    uint32_t a;
    asm("{ .reg .u64 t; cvta.to.shared.u64 t, %1; cvt.u32.u64 %0, t; }" : "=r"(a) : "l"(p));
    return a;
}
__device__ __forceinline__ uint32_t f2tf32(float f) {
    uint32_t r;
    asm("cvt.rna.tf32.f32 %0, %1;" : "=r"(r) : "f"(f));
    return r;
}
__device__ __forceinline__ void mma_tf32(float* c, const uint32_t* a, const uint32_t* b) {
    asm volatile(
        "mma.sync.aligned.m16n8k8.row.col.f32.tf32.tf32.f32 "
        "{%0,%1,%2,%3}, {%4,%5,%6,%7}, {%8,%9}, {%0,%1,%2,%3};"
        : "+f"(c[0]), "+f"(c[1]), "+f"(c[2]), "+f"(c[3])
        : "r"(a[0]), "r"(a[1]), "r"(a[2]), "r"(a[3]), "r"(b[0]), "r"(b[1]));
}
__device__ __forceinline__ void mma_f16(float* c, uint32_t a0, uint32_t a1, uint32_t a2, uint32_t a3,
                                        uint32_t b0, uint32_t b1) {
    asm volatile(
        "mma.sync.aligned.m16n8k16.row.col.f32.f16.f16.f32 "
        "{%0,%1,%2,%3}, {%4,%5,%6,%7}, {%8,%9}, {%0,%1,%2,%3};"
        : "+f"(c[0]), "+f"(c[1]), "+f"(c[2]), "+f"(c[3])
        : "r"(a0), "r"(a1), "r"(a2), "r"(a3), "r"(b0), "r"(b1));
}
#define CP_ASYNC16(smem_addr, gptr) \
    asm volatile("cp.async.cg.shared.global [%0], [%1], 16;" :: "r"(smem_addr), "l"(gptr))
#define CP_COMMIT() asm volatile("cp.async.commit_group;" ::: "memory")
#define CP_WAIT2()  asm volatile("cp.async.wait_group 2;"  ::: "memory")

// fp16 fragment permutation within each 16-value k-chunk:
//   pair p = k>>1 stored at slot (p&3)*2 + (p>>2); slot s occupies halves [2s, 2s+1].
//   Then an LDS.64 at byte 8*t within the chunk yields pairs (k=2t, k=2t+8) —
//   exactly ({a0,a2}, {a1,a3}, {b0,b1}) fragment halves of m16n8k16.

// ===========================================================================
// prep_cam: camH = permuted fp16 copy of cam  (rows of 1024, chunk = 16 halves)
// ===========================================================================
__global__ void __launch_bounds__(256)
prep_cam_kernel(const float* __restrict__ cam, __half* __restrict__ camH)
{
    const long i4 = (long)blockIdx.x * blockDim.x + threadIdx.x;  // float4 index
    const float4 v = reinterpret_cast<const float4*>(cam)[i4];
    const long row   = i4 >> 8;          // 256 float4 per 1024-row
    const int  idx4  = (int)(i4 & 255);
    const int  chunk = idx4 >> 2;
    const int  j     = idx4 & 3;
    // float4 covers pairs p=2j (slotA) and p=2j+1 (slotB)
    const int slotA = ((2 * j) & 3) * 2 + ((2 * j) >> 2);
    const int slotB = ((2 * j + 1) & 3) * 2 + ((2 * j + 1) >> 2);
    __half2* base = reinterpret_cast<__half2*>(camH + row * HW + chunk * 16);
    base[slotA] = __floats2half2_rn(v.x, v.y);
    base[slotB] = __floats2half2_rn(v.z, v.w);
}

// ===========================================================================
// Softmax: reads fp32 row of 1024, writes fp16 PERMUTED into the row's first
// 2KB (in-place; single block owns the row; reads precede writes).
// ===========================================================================
__global__ void __launch_bounds__(256)
softmax_kernel(float* __restrict__ P)
{
    __shared__ float red_m[8];
    __shared__ float red_s[8];

    const long row = blockIdx.x;
    float* rowp = P + row * (long)HW;
    const float4 v = reinterpret_cast<const float4*>(rowp)[threadIdx.x];

    const int lane = threadIdx.x & 31;
    const int warp = threadIdx.x >> 5;

    float m = fmaxf(fmaxf(v.x, v.y), fmaxf(v.z, v.w));
#pragma unroll
    for (int o = 16; o; o >>= 1) m = fmaxf(m, __shfl_xor_sync(0xffffffffu, m, o));
    if (lane == 0) red_m[warp] = m;
    __syncthreads();
    m = red_m[0];
#pragma unroll
    for (int i = 1; i < 8; i++) m = fmaxf(m, red_m[i]);

    float4 e;
    e.x = expf(v.x - m);
    e.y = expf(v.y - m);
    e.z = expf(v.z - m);
    e.w = expf(v.w - m);
    float s = e.x + e.y + e.z + e.w;
#pragma unroll
    for (int o = 16; o; o >>= 1) s += __shfl_xor_sync(0xffffffffu, s, o);
    if (lane == 0) red_s[warp] = s;
    __syncthreads();
    s = red_s[0];
#pragma unroll
    for (int i = 1; i < 8; i++) s += red_s[i];

    const float inv = 1.0f / s;
    const int chunk = threadIdx.x >> 2;
    const int j     = threadIdx.x & 3;
    const int slotA = ((2 * j) & 3) * 2 + ((2 * j) >> 2);
    const int slotB = ((2 * j + 1) & 3) * 2 + ((2 * j + 1) >> 2);
    __half2* base = reinterpret_cast<__half2*>(reinterpret_cast<__half*>(rowp) + chunk * 16);
    base[slotA] = __floats2half2_rn(e.x * inv, e.y * inv);
    base[slotB] = __floats2half2_rn(e.z * inv, e.w * inv);
}

// ===========================================================================
// GEMM3 (fp16 m16n8k16 mma.sync, pre-permuted operands, zero cvt):
//   out[b, m, n] = alpha * sum_j camH[b, m, j] * P16[b, n, j] + cam[b, m, n]
//   smem layout per stage: [2 chunks][128 rows][32B]  (conflict-free LDS.64)
// ===========================================================================
#define G3_BM 128
#define G3_BN 128
#define G3_BK 32                     // fp16 k-values per stage (2 chunks of 16)
#define G3_STAGES 4
#define G3_CHUNK_BYTES 4096          // 128 rows * 32B
#define G3_TILE_BYTES  (2 * G3_CHUNK_BYTES)          // 8KB per operand per stage
#define G3_STAGE_BYTES (2 * G3_TILE_BYTES)           // 16KB
#define G3_SMEM_BYTES  (G3_STAGES * G3_STAGE_BYTES)  // 64KB
#define G3_KITER (HW / G3_BK)        // 32

__global__ void __launch_bounds__(256, 2)
gemm3_f16_kernel(const __half* __restrict__ camH, const float* __restrict__ cam,
                 const float* __restrict__ Pf,
                 float* __restrict__ out, const float* __restrict__ alphap)
{
    extern __shared__ char smc[];

    const int tid  = threadIdx.x;
    const int wid  = tid >> 5;
    const int lane = tid & 31;
    const int g    = lane >> 2;
    const int t    = lane & 3;
    const int wm   = wid >> 1;     // 0..3
    const int wn   = wid & 1;      // 0..1

    const int b  = blockIdx.z;
    const int m0 = blockIdx.y * G3_BM;
    const int n0 = blockIdx.x * G3_BN;
    const __half* camHB = camH + (long)b * CCH * HW;
    const float*  camB  = cam  + (long)b * CCH * HW;
    // P fp16 lives in the first 2KB of each 4KB fp32 row: row n base (halves) = n*2048
    const __half* PBh = reinterpret_cast<const __half*>(Pf + (long)b * HW * HW);

    const uint32_t sm_u = smem_u32(smc);

    float acc[2][8][4];
#pragma unroll
    for (int i = 0; i < 2; i++)
#pragma unroll
        for (int j = 0; j < 8; j++)
#pragma unroll
            for (int k = 0; k < 4; k++) acc[i][j][k] = 0.f;

    auto load_stage = [&](int s, int k0 /* in halves */) {
        const uint32_t sa = sm_u + (uint32_t)(s * G3_STAGE_BYTES);
        const uint32_t sb = sa + G3_TILE_BYTES;
        // A: 8KB = 512 x 16B; 2 per thread
#pragma unroll
        for (int i = 0; i < 2; i++) {
            int c = tid + i * 256;
            int row = c >> 2, q = c & 3;                  // q = chunk*2 + half
            uint32_t dst = sa + (uint32_t)((q >> 1) * G3_CHUNK_BYTES + row * 32 + (q & 1) * 16);
            CP_ASYNC16(dst, camHB + (long)(m0 + row) * HW + k0 + q * 8);
        }
#pragma unroll
        for (int i = 0; i < 2; i++) {
            int c = tid + i * 256;
            int row = c >> 2, q = c & 3;
            uint32_t dst = sb + (uint32_t)((q >> 1) * G3_CHUNK_BYTES + row * 32 + (q & 1) * 16);
            CP_ASYNC16(dst, PBh + (long)(n0 + row) * 2048 + k0 + q * 8);
        }
    };

#pragma unroll
    for (int s = 0; s < G3_STAGES - 1; s++) {
        load_stage(s, s * G3_BK);
        CP_COMMIT();
    }

    for (int it = 0; it < G3_KITER; it++) {
        CP_WAIT2();
        __syncthreads();

        const int s = it & (G3_STAGES - 1);
        const char* sa = smc + s * G3_STAGE_BYTES;
        const char* sb = sa + G3_TILE_BYTES;

#pragma unroll
        for (int ch = 0; ch < 2; ch++) {
            const char* sac = sa + ch * G3_CHUNK_BYTES;
            const char* sbc = sb + ch * G3_CHUNK_BYTES;

            uint2 af[2][2];
#pragma unroll
            for (int mt = 0; mt < 2; mt++) {
                const int r0 = wm * 32 + mt * 16 + g;
                af[mt][0] = *reinterpret_cast<const uint2*>(sac + r0 * 32 + t * 8);        // (a0, a2)
                af[mt][1] = *reinterpret_cast<const uint2*>(sac + (r0 + 8) * 32 + t * 8);  // (a1, a3)
            }
            uint2 bf[8];
#pragma unroll
            for (int nt = 0; nt < 8; nt++) {
                const int n = wn * 64 + nt * 8 + g;
                bf[nt] = *reinterpret_cast<const uint2*>(sbc + n * 32 + t * 8);            // (b0, b1)
            }
#pragma unroll
            for (int mt = 0; mt < 2; mt++)
#pragma unroll
                for (int nt = 0; nt < 8; nt++)
                    mma_f16(acc[mt][nt], af[mt][0].x, af[mt][1].x, af[mt][0].y, af[mt][1].y,
                            bf[nt].x, bf[nt].y);
        }

        __syncthreads();
        if (it + G3_STAGES - 1 < G3_KITER)
            load_stage((it + G3_STAGES - 1) & (G3_STAGES - 1), (it + G3_STAGES - 1) * G3_BK);
        CP_COMMIT();
    }

    const float alpha = *alphap;
    float* outB = out + (long)b * CCH * HW;
#pragma unroll
    for (int mt = 0; mt < 2; mt++) {
        const int mrow = m0 + wm * 32 + mt * 16 + g;
#pragma unroll
        for (int nt = 0; nt < 8; nt++) {
            const int n = n0 + wn * 64 + nt * 8 + 2 * t;
            {
                const float2 cv = *(const float2*)(camB + (long)mrow * HW + n);
                float2 o;
                o.x = alpha * acc[mt][nt][0] + cv.x;
                o.y = alpha * acc[mt][nt][1] + cv.y;
                *(float2*)(outB + (long)mrow * HW + n) = o;
            }
            {
                const float2 cv = *(const float2*)(camB + (long)(mrow + 8) * HW + n);
                float2 o;
                o.x = alpha * acc[mt][nt][2] + cv.x;
                o.y = alpha * acc[mt][nt][3] + cv.y;
                *(float2*)(outB + (long)(mrow + 8) * HW + n) = o;
            }
        }
    }
}

// ===========================================================================
// GEMM1 / GEMM2 on tensor cores with 3xtf32 split (fp32-grade accuracy).
// (unchanged from round 4)
// ===========================================================================
#define T_BM 128
#define T_BN 128
#define T_BK 16
#define T_STAGES 4
#define PA_K 20
#define PA_M 136
#define PB_  136
#define T_ATILEF_K (T_BM * PA_K)
#define T_ATILEF_M (T_BK * PA_M)
#define T_BTILEF   (T_BK * PB_)
#define T_ATILEF_MAX T_ATILEF_K
#define T_STAGEF (T_ATILEF_MAX + T_BTILEF)
#define T_SMEM_BYTES (T_STAGES * T_STAGEF * 4)

template<bool AKC>
__global__ void __launch_bounds__(256, 2)
mma3_gemm_kernel(const float* __restrict__ Ag, const float* __restrict__ Bg,
                 float* __restrict__ Cg,
                 int M, int N, int K,
                 long sA, long sB, long sC)
{
    extern __shared__ float sm[];

    const int tid  = threadIdx.x;
    const int wid  = tid >> 5;
    const int lane = tid & 31;
    const int g    = lane >> 2;
    const int t    = lane & 3;
    const int wm   = wid >> 1;
    const int wn   = wid & 1;

    const int b  = blockIdx.z;
    const int m0 = blockIdx.y * T_BM;
    const int n0 = blockIdx.x * T_BN;
    const float* A = Ag + (long)b * sA;
    const float* B = Bg + (long)b * sB;
    float* C = Cg + (long)b * sC;

    const uint32_t sm_u = smem_u32(sm);
    const int kIter = K / T_BK;

    float acc[2][8][4];
#pragma unroll
    for (int i = 0; i < 2; i++)
#pragma unroll
        for (int j = 0; j < 8; j++)
#pragma unroll
            for (int k = 0; k < 4; k++) acc[i][j][k] = 0.f;

    auto load_stage = [&](int s, int k0) {
        const uint32_t sa = sm_u + (uint32_t)(s * T_STAGEF) * 4u;
        const uint32_t sb = sa + (uint32_t)T_ATILEF_MAX * 4u;
        if (AKC) {
#pragma unroll
            for (int i = 0; i < 2; i++) {
                int c = tid + i * 256;
                int row = c >> 2, cc = c & 3;
                CP_ASYNC16(sa + (uint32_t)(row * PA_K + cc * 4) * 4u,
                           A + (long)(m0 + row) * K + k0 + cc * 4);
            }
        } else {
#pragma unroll
            for (int i = 0; i < 2; i++) {
                int c = tid + i * 256;
                int k = c >> 5, cc = c & 31;
                CP_ASYNC16(sa + (uint32_t)(k * PA_M + cc * 4) * 4u,
                           A + (long)(k0 + k) * M + m0 + cc * 4);
            }
        }
#pragma unroll
        for (int i = 0; i < 2; i++) {
            int c = tid + i * 256;
            int k = c >> 5, cc = c & 31;
            CP_ASYNC16(sb + (uint32_t)(k * PB_ + cc * 4) * 4u,
                       B + (long)(k0 + k) * N + n0 + cc * 4);
        }
    };

#pragma unroll
    for (int s = 0; s < T_STAGES - 1; s++) {
        load_stage(s, s * T_BK);
        CP_COMMIT();
    }

    for (int it = 0; it < kIter; it++) {
        CP_WAIT2();
        __syncthreads();

        const int s = it & (T_STAGES - 1);
        const float* sa = sm + s * T_STAGEF;
        const float* sb = sa + T_ATILEF_MAX;

#pragma unroll
        for (int step = 0; step < 2; step++) {
            const int kk = step * 8;
            uint32_t ahi[2][4], alo[2][4];
#pragma unroll
            for (int mt = 0; mt < 2; mt++) {
                const int r0 = wm * 32 + mt * 16 + g;
                float x[4];
                if (AKC) {
                    x[0] = sa[r0 * PA_K + kk + t];
                    x[1] = sa[(r0 + 8) * PA_K + kk + t];
                    x[2] = sa[r0 * PA_K + kk + t + 4];
                    x[3] = sa[(r0 + 8) * PA_K + kk + t + 4];
                } else {
                    x[0] = sa[(kk + t) * PA_M + r0];
                    x[1] = sa[(kk + t) * PA_M + r0 + 8];
                    x[2] = sa[(kk + t + 4) * PA_M + r0];
                    x[3] = sa[(kk + t + 4) * PA_M + r0 + 8];
                }
#pragma unroll
                for (int q = 0; q < 4; q++) {
                    ahi[mt][q] = f2tf32(x[q]);
                    alo[mt][q] = f2tf32(x[q] - __uint_as_float(ahi[mt][q]));
                }
            }
#pragma unroll
            for (int nt = 0; nt < 8; nt++) {
                const int n = wn * 64 + nt * 8 + g;
                const float y0 = sb[(kk + t) * PB_ + n];
                const float y1 = sb[(kk + t + 4) * PB_ + n];
                uint32_t bhi[2], blo[2];
                bhi[0] = f2tf32(y0); blo[0] = f2tf32(y0 - __uint_as_float(bhi[0]));
                bhi[1] = f2tf32(y1); blo[1] = f2tf32(y1 - __uint_as_float(bhi[1]));
#pragma unroll
                for (int mt = 0; mt < 2; mt++) {
                    mma_tf32(acc[mt][nt], ahi[mt], bhi);
                    mma_tf32(acc[mt][nt], ahi[mt], blo);
                    mma_tf32(acc[mt][nt], alo[mt], bhi);
                }
            }
        }

        __syncthreads();
        if (it + T_STAGES - 1 < kIter)
            load_stage((it + T_STAGES - 1) & (T_STAGES - 1), (it + T_STAGES - 1) * T_BK);
        CP_COMMIT();
    }

#pragma unroll
    for (int mt = 0; mt < 2; mt++) {
        const int mrow = m0 + wm * 32 + mt * 16 + g;
#pragma unroll
        for (int nt = 0; nt < 8; nt++) {
            const int n = n0 + wn * 64 + nt * 8 + 2 * t;
            *(float2*)(C + (long)mrow * N + n) = make_float2(acc[mt][nt][0], acc[mt][nt][1]);
            *(float2*)(C + (long)(mrow + 8) * N + n) = make_float2(acc[mt][nt][2], acc[mt][nt][3]);
        }
    }
}

// ---------------------------------------------------------------------------
extern "C" void kernel_launch(void* const* d_in, const int* in_sizes, int n_in,
                              void* d_out, int out_size)
{
    const float* feat  = (const float*)d_in[0];
    const float* cam   = (const float*)d_in[1];
    const float* Wq    = (const float*)d_in[2];
    const float* Wk    = (const float*)d_in[3];
    const float* alpha = (const float*)d_in[4];
    float* out = (float*)d_out;

    float *w, *f12, *P;
    __half* camH;
    cudaGetSymbolAddress((void**)&w, g_W);
    cudaGetSymbolAddress((void**)&f12, g_f12);
    cudaGetSymbolAddress((void**)&P, g_P);
    cudaGetSymbolAddress((void**)&camH, g_camH);

    // concat Wq / Wk into one [256, 2048] matrix
    cudaMemcpyAsync(w,             Wq, (size_t)MID * CCH * sizeof(float), cudaMemcpyDeviceToDevice);
    cudaMemcpyAsync(w + MID * CCH, Wk, (size_t)MID * CCH * sizeof(float), cudaMemcpyDeviceToDevice);

    // prep: permuted fp16 copy of cam for GEMM3 A-operand
    {
        long n4 = (long)BATCH * CCH * HW / 4;
        prep_cam_kernel<<<(unsigned)(n4 / 256), 256>>>(cam, camH);
    }

    // GEMM1 (3xtf32): f12[b, m, n] = W[m, k] * feat[b, k, n]   (M=256, N=1024, K=2048)
    {
        cudaFuncSetAttribute(mma3_gemm_kernel<true>,
                             cudaFuncAttributeMaxDynamicSharedMemorySize, T_SMEM_BYTES);
        dim3 grid(HW / T_BN, (2 * MID) / T_BM, BATCH);
        mma3_gemm_kernel<true><<<grid, 256, T_SMEM_BYTES>>>(
            w, feat, f12,
            2 * MID, HW, CCH,
            0L, (long)CCH * HW, (long)2 * MID * HW);
    }

    // GEMM2 (3xtf32): S[b, i, j] = sum_m f1[b, m, i] * f2[b, m, j]  (M=N=1024, K=128)
    {
        cudaFuncSetAttribute(mma3_gemm_kernel<false>,
                             cudaFuncAttributeMaxDynamicSharedMemorySize, T_SMEM_BYTES);
        dim3 grid(HW / T_BN, HW / T_BM, BATCH);
        mma3_gemm_kernel<false><<<grid, 256, T_SMEM_BYTES>>>(
            f12, f12 + (long)MID * HW, P,
            HW, HW, MID,
            (long)2 * MID * HW, (long)2 * MID * HW, (long)HW * HW);
    }

    // Softmax (writes P as permuted fp16, in-place, ready for GEMM3 fragments)
    softmax_kernel<<<BATCH * HW, 256>>>(P);

    // GEMM3 (fp16 m16n8k16): out = alpha * cam @ P^T + cam
    {
        cudaFuncSetAttribute(gemm3_f16_kernel,
                             cudaFuncAttributeMaxDynamicSharedMemorySize, G3_SMEM_BYTES);
        dim3 grid(HW / G3_BN, CCH / G3_BM, BATCH);
        gemm3_f16_kernel<<<grid, 256, G3_SMEM_BYTES>>>(camH, cam, P, out, alpha);
    }
}

// round 6
// speedup vs baseline: 3.3996x; 1.2351x over previous
#include <cuda_runtime.h>
#include <cuda_fp16.h>
#include <cstdint>

// Problem constants
#define BATCH 32
#define CCH   2048
#define HW    1024
#define MID   128

// Scratch (allocation-free rule: __device__ globals)
static __device__ float  g_W[2 * MID * CCH];                  // 2 MB
static __device__ float  g_f12[(long)BATCH * 2 * MID * HW];   // 32 MB
static __device__ float  g_P[(long)BATCH * HW * HW];          // 128 MB
static __device__ __half g_camH[(long)BATCH * CCH * HW];      // 128 MB

// ===========================================================================
// Helpers
// ===========================================================================
__device__ __forceinline__ uint32_t smem_u32(const void* p) {
    uint32_t a;
    asm("{ .reg .u64 t; cvta.to.shared.u64 t, %1; cvt.u32.u64 %0, t; }" : "=r"(a) : "l"(p));
    return a;
}
__device__ __forceinline__ void mma_f16(float* c, uint32_t a0, uint32_t a1, uint32_t a2, uint32_t a3,
                                        uint32_t b0, uint32_t b1) {
    asm volatile(
        "mma.sync.aligned.m16n8k16.row.col.f32.f16.f16.f32 "
        "{%0,%1,%2,%3}, {%4,%5,%6,%7}, {%8,%9}, {%0,%1,%2,%3};"
        : "+f"(c[0]), "+f"(c[1]), "+f"(c[2]), "+f"(c[3])
        : "r"(a0), "r"(a1), "r"(a2), "r"(a3), "r"(b0), "r"(b1));
}
__device__ __forceinline__ void mma_bf16(float* c, const uint32_t* a, uint32_t b0, uint32_t b1) {
    asm volatile(
        "mma.sync.aligned.m16n8k16.row.col.f32.bf16.bf16.f32 "
        "{%0,%1,%2,%3}, {%4,%5,%6,%7}, {%8,%9}, {%0,%1,%2,%3};"
        : "+f"(c[0]), "+f"(c[1]), "+f"(c[2]), "+f"(c[3])
        : "r"(a[0]), "r"(a[1]), "r"(a[2]), "r"(a[3]), "r"(b0), "r"(b1));
}
// pack (k_even, k_odd) into bf16x2: lower half = k_even
__device__ __forceinline__ uint32_t bf16x2_pack(float e, float o) {
    uint32_t r;
    asm("cvt.rn.bf16x2.f32 %0, %1, %2;" : "=r"(r) : "f"(o), "f"(e));
    return r;
}
__device__ __forceinline__ uint32_t bf16x2_residual(float e, float o, uint32_t hi) {
    const float he = __uint_as_float(hi << 16);
    const float ho = __uint_as_float(hi & 0xffff0000u);
    return bf16x2_pack(e - he, o - ho);
}
#define CP_ASYNC16(smem_addr, gptr) \
    asm volatile("cp.async.cg.shared.global [%0], [%1], 16;" :: "r"(smem_addr), "l"(gptr))
#define CP_COMMIT() asm volatile("cp.async.commit_group;" ::: "memory")
#define CP_WAIT2()  asm volatile("cp.async.wait_group 2;"  ::: "memory")

// ===========================================================================
// prep_cam: camH = permuted fp16 copy of cam (pair p -> slot (p&3)*2+(p>>2))
// ===========================================================================
__global__ void __launch_bounds__(256)
prep_cam_kernel(const float* __restrict__ cam, __half* __restrict__ camH)
{
    const long i4 = (long)blockIdx.x * blockDim.x + threadIdx.x;
    const float4 v = reinterpret_cast<const float4*>(cam)[i4];
    const long row   = i4 >> 8;
    const int  idx4  = (int)(i4 & 255);
    const int  chunk = idx4 >> 2;
    const int  j     = idx4 & 3;
    const int slotA = ((2 * j) & 3) * 2 + ((2 * j) >> 2);
    const int slotB = ((2 * j + 1) & 3) * 2 + ((2 * j + 1) >> 2);
    __half2* base = reinterpret_cast<__half2*>(camH + row * HW + chunk * 16);
    base[slotA] = __floats2half2_rn(v.x, v.y);
    base[slotB] = __floats2half2_rn(v.z, v.w);
}

// ===========================================================================
// Softmax: fp32 row of 1024 -> fp16 permuted, in-place
// ===========================================================================
__global__ void __launch_bounds__(256)
softmax_kernel(float* __restrict__ P)
{
    __shared__ float red_m[8];
    __shared__ float red_s[8];

    const long row = blockIdx.x;
    float* rowp = P + row * (long)HW;
    const float4 v = reinterpret_cast<const float4*>(rowp)[threadIdx.x];

    const int lane = threadIdx.x & 31;
    const int warp = threadIdx.x >> 5;

    float m = fmaxf(fmaxf(v.x, v.y), fmaxf(v.z, v.w));
#pragma unroll
    for (int o = 16; o; o >>= 1) m = fmaxf(m, __shfl_xor_sync(0xffffffffu, m, o));
    if (lane == 0) red_m[warp] = m;
    __syncthreads();
    m = red_m[0];
#pragma unroll
    for (int i = 1; i < 8; i++) m = fmaxf(m, red_m[i]);

    float4 e;
    e.x = expf(v.x - m);
    e.y = expf(v.y - m);
    e.z = expf(v.z - m);
    e.w = expf(v.w - m);
    float s = e.x + e.y + e.z + e.w;
#pragma unroll
    for (int o = 16; o; o >>= 1) s += __shfl_xor_sync(0xffffffffu, s, o);
    if (lane == 0) red_s[warp] = s;
    __syncthreads();
    s = red_s[0];
#pragma unroll
    for (int i = 1; i < 8; i++) s += red_s[i];

    const float inv = 1.0f / s;
    const int chunk = threadIdx.x >> 2;
    const int j     = threadIdx.x & 3;
    const int slotA = ((2 * j) & 3) * 2 + ((2 * j) >> 2);
    const int slotB = ((2 * j + 1) & 3) * 2 + ((2 * j + 1) >> 2);
    __half2* base = reinterpret_cast<__half2*>(reinterpret_cast<__half*>(rowp) + chunk * 16);
    base[slotA] = __floats2half2_rn(e.x * inv, e.y * inv);
    base[slotB] = __floats2half2_rn(e.z * inv, e.w * inv);
}

// ===========================================================================
// GEMM3 (fp16 m16n8k16, pre-permuted operands) — unchanged from round 5
// ===========================================================================
#define G3_BM 128
#define G3_BN 128
#define G3_BK 32
#define G3_STAGES 4
#define G3_CHUNK_BYTES 4096
#define G3_TILE_BYTES  (2 * G3_CHUNK_BYTES)
#define G3_STAGE_BYTES (2 * G3_TILE_BYTES)
#define G3_SMEM_BYTES  (G3_STAGES * G3_STAGE_BYTES)
#define G3_KITER (HW / G3_BK)

__global__ void __launch_bounds__(256, 2)
gemm3_f16_kernel(const __half* __restrict__ camH, const float* __restrict__ cam,
                 const float* __restrict__ Pf,
                 float* __restrict__ out, const float* __restrict__ alphap)
{
    extern __shared__ char smc[];

    const int tid  = threadIdx.x;
    const int wid  = tid >> 5;
    const int lane = tid & 31;
    const int g    = lane >> 2;
    const int t    = lane & 3;
    const int wm   = wid >> 1;
    const int wn   = wid & 1;

    const int b  = blockIdx.z;
    const int m0 = blockIdx.y * G3_BM;
    const int n0 = blockIdx.x * G3_BN;
    const __half* camHB = camH + (long)b * CCH * HW;
    const float*  camB  = cam  + (long)b * CCH * HW;
    const __half* PBh = reinterpret_cast<const __half*>(Pf + (long)b * HW * HW);

    const uint32_t sm_u = smem_u32(smc);

    float acc[2][8][4];
#pragma unroll
    for (int i = 0; i < 2; i++)
#pragma unroll
        for (int j = 0; j < 8; j++)
#pragma unroll
            for (int k = 0; k < 4; k++) acc[i][j][k] = 0.f;

    auto load_stage = [&](int s, int k0) {
        const uint32_t sa = sm_u + (uint32_t)(s * G3_STAGE_BYTES);
        const uint32_t sb = sa + G3_TILE_BYTES;
#pragma unroll
        for (int i = 0; i < 2; i++) {
            int c = tid + i * 256;
            int row = c >> 2, q = c & 3;
            uint32_t dst = sa + (uint32_t)((q >> 1) * G3_CHUNK_BYTES + row * 32 + (q & 1) * 16);
            CP_ASYNC16(dst, camHB + (long)(m0 + row) * HW + k0 + q * 8);
        }
#pragma unroll
        for (int i = 0; i < 2; i++) {
            int c = tid + i * 256;
            int row = c >> 2, q = c & 3;
            uint32_t dst = sb + (uint32_t)((q >> 1) * G3_CHUNK_BYTES + row * 32 + (q & 1) * 16);
            CP_ASYNC16(dst, PBh + (long)(n0 + row) * 2048 + k0 + q * 8);
        }
    };

#pragma unroll
    for (int s = 0; s < G3_STAGES - 1; s++) {
        load_stage(s, s * G3_BK);
        CP_COMMIT();
    }

    for (int it = 0; it < G3_KITER; it++) {
        CP_WAIT2();
        __syncthreads();

        const int s = it & (G3_STAGES - 1);
        const char* sa = smc + s * G3_STAGE_BYTES;
        const char* sb = sa + G3_TILE_BYTES;

#pragma unroll
        for (int ch = 0; ch < 2; ch++) {
            const char* sac = sa + ch * G3_CHUNK_BYTES;
            const char* sbc = sb + ch * G3_CHUNK_BYTES;

            uint2 af[2][2];
#pragma unroll
            for (int mt = 0; mt < 2; mt++) {
                const int r0 = wm * 32 + mt * 16 + g;
                af[mt][0] = *reinterpret_cast<const uint2*>(sac + r0 * 32 + t * 8);
                af[mt][1] = *reinterpret_cast<const uint2*>(sac + (r0 + 8) * 32 + t * 8);
            }
            uint2 bf[8];
#pragma unroll
            for (int nt = 0; nt < 8; nt++) {
                const int n = wn * 64 + nt * 8 + g;
                bf[nt] = *reinterpret_cast<const uint2*>(sbc + n * 32 + t * 8);
            }
#pragma unroll
            for (int mt = 0; mt < 2; mt++)
#pragma unroll
                for (int nt = 0; nt < 8; nt++)
                    mma_f16(acc[mt][nt], af[mt][0].x, af[mt][1].x, af[mt][0].y, af[mt][1].y,
                            bf[nt].x, bf[nt].y);
        }

        __syncthreads();
        if (it + G3_STAGES - 1 < G3_KITER)
            load_stage((it + G3_STAGES - 1) & (G3_STAGES - 1), (it + G3_STAGES - 1) * G3_BK);
        CP_COMMIT();
    }

    const float alpha = *alphap;
    float* outB = out + (long)b * CCH * HW;
#pragma unroll
    for (int mt = 0; mt < 2; mt++) {
        const int mrow = m0 + wm * 32 + mt * 16 + g;
#pragma unroll
        for (int nt = 0; nt < 8; nt++) {
            const int n = n0 + wn * 64 + nt * 8 + 2 * t;
            {
                const float2 cv = *(const float2*)(camB + (long)mrow * HW + n);
                float2 o;
                o.x = alpha * acc[mt][nt][0] + cv.x;
                o.y = alpha * acc[mt][nt][1] + cv.y;
                *(float2*)(outB + (long)mrow * HW + n) = o;
            }
            {
                const float2 cv = *(const float2*)(camB + (long)(mrow + 8) * HW + n);
                float2 o;
                o.x = alpha * acc[mt][nt][2] + cv.x;
                o.y = alpha * acc[mt][nt][3] + cv.y;
                *(float2*)(outB + (long)(mrow + 8) * HW + n) = o;
            }
        }
    }
}

// ===========================================================================
// GEMM1 / GEMM2: bf16 3-way split on m16n8k16 (fp32-grade accuracy, half the
// per-K instruction cost of the old 3xtf32 m16n8k8 path).
//   C[b, m, n] = sum_k A(m,k) * B(k,n)
//   AKC=true : A stored [M][K] (K contig)   — GEMM1 (A = W)
//   AKC=false: A stored [K][M] (M contig)   — GEMM2 (A = f1)
//   B stored [K][N] (N contig) in both.
// ===========================================================================
#define T_BM 128
#define T_BN 128
#define T_BK 16
#define T_STAGES 4
#define PA_K 20
#define PA_M 136
#define PB_  136
#define T_ATILEF_K (T_BM * PA_K)
#define T_BTILEF   (T_BK * PB_)
#define T_ATILEF_MAX T_ATILEF_K
#define T_STAGEF (T_ATILEF_MAX + T_BTILEF)
#define T_SMEM_BYTES (T_STAGES * T_STAGEF * 4)

template<bool AKC>
__global__ void __launch_bounds__(256, 2)
mma3_gemm_kernel(const float* __restrict__ Ag, const float* __restrict__ Bg,
                 float* __restrict__ Cg,
                 int M, int N, int K,
                 long sA, long sB, long sC)
{
    extern __shared__ float sm[];

    const int tid  = threadIdx.x;
    const int wid  = tid >> 5;
    const int lane = tid & 31;
    const int g    = lane >> 2;
    const int t    = lane & 3;
    const int wm   = wid >> 1;
    const int wn   = wid & 1;

    const int b  = blockIdx.z;
    const int m0 = blockIdx.y * T_BM;
    const int n0 = blockIdx.x * T_BN;
    const float* A = Ag + (long)b * sA;
    const float* B = Bg + (long)b * sB;
    float* C = Cg + (long)b * sC;

    const uint32_t sm_u = smem_u32(sm);
    const int kIter = K / T_BK;

    float acc[2][8][4];
#pragma unroll
    for (int i = 0; i < 2; i++)
#pragma unroll
        for (int j = 0; j < 8; j++)
#pragma unroll
            for (int k = 0; k < 4; k++) acc[i][j][k] = 0.f;

    auto load_stage = [&](int s, int k0) {
        const uint32_t sa = sm_u + (uint32_t)(s * T_STAGEF) * 4u;
        const uint32_t sb = sa + (uint32_t)T_ATILEF_MAX * 4u;
        if (AKC) {
#pragma unroll
            for (int i = 0; i < 2; i++) {
                int c = tid + i * 256;
                int row = c >> 2, cc = c & 3;
                CP_ASYNC16(sa + (uint32_t)(row * PA_K + cc * 4) * 4u,
                           A + (long)(m0 + row) * K + k0 + cc * 4);
            }
        } else {
#pragma unroll
            for (int i = 0; i < 2; i++) {
                int c = tid + i * 256;
                int k = c >> 5, cc = c & 31;
                CP_ASYNC16(sa + (uint32_t)(k * PA_M + cc * 4) * 4u,
                           A + (long)(k0 + k) * M + m0 + cc * 4);
            }
        }
#pragma unroll
        for (int i = 0; i < 2; i++) {
            int c = tid + i * 256;
            int k = c >> 5, cc = c & 31;
            CP_ASYNC16(sb + (uint32_t)(k * PB_ + cc * 4) * 4u,
                       B + (long)(k0 + k) * N + n0 + cc * 4);
        }
    };

#pragma unroll
    for (int s = 0; s < T_STAGES - 1; s++) {
        load_stage(s, s * T_BK);
        CP_COMMIT();
    }

    const int k_e = 2 * t;        // even k of the low-half pair
    const int k_o = 2 * t + 1;

    for (int it = 0; it < kIter; it++) {
        CP_WAIT2();
        __syncthreads();

        const int s = it & (T_STAGES - 1);
        const float* sa = sm + s * T_STAGEF;
        const float* sb = sa + T_ATILEF_MAX;

        // A fragments: regs hold k-pairs (k_e,k_o) and (k_e+8,k_o+8)
        uint32_t ahi[2][4], alo[2][4];
#pragma unroll
        for (int mt = 0; mt < 2; mt++) {
            const int r0 = wm * 32 + mt * 16 + g;
            float2 p[4];
            if (AKC) {
                p[0] = *reinterpret_cast<const float2*>(sa + r0 * PA_K + k_e);
                p[1] = *reinterpret_cast<const float2*>(sa + (r0 + 8) * PA_K + k_e);
                p[2] = *reinterpret_cast<const float2*>(sa + r0 * PA_K + k_e + 8);
                p[3] = *reinterpret_cast<const float2*>(sa + (r0 + 8) * PA_K + k_e + 8);
            } else {
                p[0] = make_float2(sa[k_e * PA_M + r0],       sa[k_o * PA_M + r0]);
                p[1] = make_float2(sa[k_e * PA_M + r0 + 8],   sa[k_o * PA_M + r0 + 8]);
                p[2] = make_float2(sa[(k_e + 8) * PA_M + r0],     sa[(k_o + 8) * PA_M + r0]);
                p[3] = make_float2(sa[(k_e + 8) * PA_M + r0 + 8], sa[(k_o + 8) * PA_M + r0 + 8]);
            }
#pragma unroll
            for (int q = 0; q < 4; q++) {
                ahi[mt][q] = bf16x2_pack(p[q].x, p[q].y);
                alo[mt][q] = bf16x2_residual(p[q].x, p[q].y, ahi[mt][q]);
            }
        }

#pragma unroll
        for (int nt = 0; nt < 8; nt++) {
            const int n = wn * 64 + nt * 8 + g;
            const float e0 = sb[k_e * PB_ + n];
            const float o0 = sb[k_o * PB_ + n];
            const float e1 = sb[(k_e + 8) * PB_ + n];
            const float o1 = sb[(k_o + 8) * PB_ + n];
            const uint32_t bhi0 = bf16x2_pack(e0, o0);
            const uint32_t blo0 = bf16x2_residual(e0, o0, bhi0);
            const uint32_t bhi1 = bf16x2_pack(e1, o1);
            const uint32_t blo1 = bf16x2_residual(e1, o1, bhi1);
#pragma unroll
            for (int mt = 0; mt < 2; mt++) {
                mma_bf16(acc[mt][nt], ahi[mt], bhi0, bhi1);
                mma_bf16(acc[mt][nt], ahi[mt], blo0, blo1);
                mma_bf16(acc[mt][nt], alo[mt], bhi0, bhi1);
            }
        }

        __syncthreads();
        if (it + T_STAGES - 1 < kIter)
            load_stage((it + T_STAGES - 1) & (T_STAGES - 1), (it + T_STAGES - 1) * T_BK);
        CP_COMMIT();
    }

#pragma unroll
    for (int mt = 0; mt < 2; mt++) {
        const int mrow = m0 + wm * 32 + mt * 16 + g;
#pragma unroll
        for (int nt = 0; nt < 8; nt++) {
            const int n = n0 + wn * 64 + nt * 8 + 2 * t;
            *(float2*)(C + (long)mrow * N + n) = make_float2(acc[mt][nt][0], acc[mt][nt][1]);
            *(float2*)(C + (long)(mrow + 8) * N + n) = make_float2(acc[mt][nt][2], acc[mt][nt][3]);
        }
    }
}

// ---------------------------------------------------------------------------
extern "C" void kernel_launch(void* const* d_in, const int* in_sizes, int n_in,
                              void* d_out, int out_size)
{
    const float* feat  = (const float*)d_in[0];
    const float* cam   = (const float*)d_in[1];
    const float* Wq    = (const float*)d_in[2];
    const float* Wk    = (const float*)d_in[3];
    const float* alpha = (const float*)d_in[4];
    float* out = (float*)d_out;

    float *w, *f12, *P;
    __half* camH;
    cudaGetSymbolAddress((void**)&w, g_W);
    cudaGetSymbolAddress((void**)&f12, g_f12);
    cudaGetSymbolAddress((void**)&P, g_P);
    cudaGetSymbolAddress((void**)&camH, g_camH);

    cudaMemcpyAsync(w,             Wq, (size_t)MID * CCH * sizeof(float), cudaMemcpyDeviceToDevice);
    cudaMemcpyAsync(w + MID * CCH, Wk, (size_t)MID * CCH * sizeof(float), cudaMemcpyDeviceToDevice);

    // prep: permuted fp16 copy of cam for GEMM3 A-operand
    {
        long n4 = (long)BATCH * CCH * HW / 4;
        prep_cam_kernel<<<(unsigned)(n4 / 256), 256>>>(cam, camH);
    }

    // GEMM1 (3xbf16): f12[b, m, n] = W[m, k] * feat[b, k, n]
    {
        cudaFuncSetAttribute(mma3_gemm_kernel<true>,
                             cudaFuncAttributeMaxDynamicSharedMemorySize, T_SMEM_BYTES);
        dim3 grid(HW / T_BN, (2 * MID) / T_BM, BATCH);
        mma3_gemm_kernel<true><<<grid, 256, T_SMEM_BYTES>>>(
            w, feat, f12,
            2 * MID, HW, CCH,
            0L, (long)CCH * HW, (long)2 * MID * HW);
    }

    // GEMM2 (3xbf16): S[b, i, j] = sum_m f1[b, m, i] * f2[b, m, j]
    {
        cudaFuncSetAttribute(mma3_gemm_kernel<false>,
                             cudaFuncAttributeMaxDynamicSharedMemorySize, T_SMEM_BYTES);
        dim3 grid(HW / T_BN, HW / T_BM, BATCH);
        mma3_gemm_kernel<false><<<grid, 256, T_SMEM_BYTES>>>(
            f12, f12 + (long)MID * HW, P,
            HW, HW, MID,
            (long)2 * MID * HW, (long)2 * MID * HW, (long)HW * HW);
    }

    // Softmax (fp32 -> permuted fp16, in-place)
    softmax_kernel<<<BATCH * HW, 256>>>(P);

    // GEMM3 (fp16 m16n8k16): out = alpha * cam @ P^T + cam
    {
        cudaFuncSetAttribute(gemm3_f16_kernel,
                             cudaFuncAttributeMaxDynamicSharedMemorySize, G3_SMEM_BYTES);
        dim3 grid(HW / G3_BN, CCH / G3_BM, BATCH);
        gemm3_f16_kernel<<<grid, 256, G3_SMEM_BYTES>>>(camH, cam, P, out, alpha);
    }
}

// round 7
// speedup vs baseline: 3.4357x; 1.0106x over previous
#include <cuda_runtime.h>
#include <cuda_fp16.h>
#include <cstdint>

// Problem constants
#define BATCH 32
#define CCH   2048
#define HW    1024
#define MID   128

// Scratch (allocation-free rule: __device__ globals)
static __device__ float    g_f12[(long)BATCH * 2 * MID * HW];          // 32 MB fp32 (GEMM1 out)
static __device__ float    g_P[(long)BATCH * HW * HW];                 // 128 MB
static __device__ __half   g_camH[(long)BATCH * CCH * HW];             // 128 MB
static __device__ uint32_t g_Wpk[128 * 4096];                          // 2 MB   packed W (256 rows, 128 chunks)
static __device__ uint32_t g_featPk[(long)BATCH * 128 * 2 * HW * 8];   // 256 MB packed feat
static __device__ uint32_t g_f12pk[(long)BATCH * 16 * 2 * HW * 8];     // 32 MB  packed f12

// ===========================================================================
// Helpers
// ===========================================================================
__device__ __forceinline__ uint32_t smem_u32(const void* p) {
    uint32_t a;
    asm("{ .reg .u64 t; cvta.to.shared.u64 t, %1; cvt.u32.u64 %0, t; }" : "=r"(a) : "l"(p));
    return a;
}
__device__ __forceinline__ void mma_f16(float* c, uint32_t a0, uint32_t a1, uint32_t a2, uint32_t a3,
                                        uint32_t b0, uint32_t b1) {
    asm volatile(
        "mma.sync.aligned.m16n8k16.row.col.f32.f16.f16.f32 "
        "{%0,%1,%2,%3}, {%4,%5,%6,%7}, {%8,%9}, {%0,%1,%2,%3};"
        : "+f"(c[0]), "+f"(c[1]), "+f"(c[2]), "+f"(c[3])
        : "r"(a0), "r"(a1), "r"(a2), "r"(a3), "r"(b0), "r"(b1));
}
__device__ __forceinline__ void mma_bf16(float* c, const uint32_t* a, uint32_t b0, uint32_t b1) {
    asm volatile(
        "mma.sync.aligned.m16n8k16.row.col.f32.bf16.bf16.f32 "
        "{%0,%1,%2,%3}, {%4,%5,%6,%7}, {%8,%9}, {%0,%1,%2,%3};"
        : "+f"(c[0]), "+f"(c[1]), "+f"(c[2]), "+f"(c[3])
        : "r"(a[0]), "r"(a[1]), "r"(a[2]), "r"(a[3]), "r"(b0), "r"(b1));
}
__device__ __forceinline__ uint32_t bf16x2_pack(float e, float o) {
    uint32_t r;
    asm("cvt.rn.bf16x2.f32 %0, %1, %2;" : "=r"(r) : "f"(o), "f"(e));
    return r;
}
__device__ __forceinline__ uint32_t bf16x2_residual(float e, float o, uint32_t hi) {
    const float he = __uint_as_float(hi << 16);
    const float ho = __uint_as_float(hi & 0xffff0000u);
    return bf16x2_pack(e - he, o - ho);
}
#define CP_ASYNC16(smem_addr, gptr) \
    asm volatile("cp.async.cg.shared.global [%0], [%1], 16;" :: "r"(smem_addr), "l"(gptr))
#define CP_COMMIT() asm volatile("cp.async.commit_group;" ::: "memory")
#define CP_WAIT2()  asm volatile("cp.async.wait_group 2;"  ::: "memory")

// Packed format, per K-chunk of 16: [chunk][hl][row][8 uint32 slots].
// Pair u = (k=2u, 2u+1); slot position p(u) = 2u (u<4) else 2(u-4)+1.
// LDS.64 at slot offset 2t then yields (pair u=t, pair u=t+4) = frag regs
// (low-k, high-k) for one mma row/col. hi plane = bf16x2 round, lo = residual.

// ===========================================================================
// prep_w: Wq/Wk [128][2048] each -> packed [128 chunks][hl][256 rows][8]
// ===========================================================================
__global__ void __launch_bounds__(256)
prep_w_kernel(const float* __restrict__ Wq, const float* __restrict__ Wk,
              uint32_t* __restrict__ Wpk)
{
    const int idx = blockIdx.x * 256 + threadIdx.x;   // 32768 = 256 rows x 128 chunks
    const int m = idx >> 7;
    const int c = idx & 127;
    const float* src = (m < 128 ? Wq + (long)m * CCH : Wk + (long)(m - 128) * CCH) + c * 16;

    float f[16];
#pragma unroll
    for (int q = 0; q < 4; q++)
        *reinterpret_cast<float4*>(f + q * 4) = *reinterpret_cast<const float4*>(src + q * 4);

    uint32_t hi[8], lo[8];
#pragma unroll
    for (int u = 0; u < 8; u++) {
        const int p = (u < 4) ? 2 * u : 2 * u - 7;
        hi[p] = bf16x2_pack(f[2 * u], f[2 * u + 1]);
        lo[p] = bf16x2_residual(f[2 * u], f[2 * u + 1], hi[p]);
    }
    uint32_t* dhi = Wpk + (long)c * 4096 + m * 8;        // chunk stride 2*256*8
    uint32_t* dlo = dhi + 2048;                          // hl stride 256*8
#pragma unroll
    for (int q = 0; q < 8; q++) { dhi[q] = hi[q]; dlo[q] = lo[q]; }
}

// ===========================================================================
// pack_rows: generic [C][n] fp32 -> packed (pairs across first dim).
//   thread per (b, c, n): 16 strided reads (warp-coalesced), 64B write.
//   Cdim = number of K values (rows), chunks = Cdim/16.
// ===========================================================================
__global__ void __launch_bounds__(256)
pack_rows_kernel(const float* __restrict__ src, uint32_t* __restrict__ dst,
                 int chunks /* per batch */)
{
    const long idx = (long)blockIdx.x * 256 + threadIdx.x;    // (b*chunks + c)*1024 + n
    const int  n   = (int)(idx & (HW - 1));
    const long bc  = idx >> 10;
    const int  c   = (int)(bc % chunks);
    const long b   = bc / chunks;

    const float* s = src + (b * chunks + c) * 16 * (long)HW + n;
    float f[16];
#pragma unroll
    for (int j = 0; j < 16; j++) f[j] = s[(long)j * HW];

    uint32_t hi[8], lo[8];
#pragma unroll
    for (int u = 0; u < 8; u++) {
        const int p = (u < 4) ? 2 * u : 2 * u - 7;
        hi[p] = bf16x2_pack(f[2 * u], f[2 * u + 1]);
        lo[p] = bf16x2_residual(f[2 * u], f[2 * u + 1], hi[p]);
    }
    uint32_t* base = dst + (b * chunks + c) * (long)(2 * HW * 8) + n * 8;
#pragma unroll
    for (int q = 0; q < 2; q++) {
        *reinterpret_cast<uint4*>(base + q * 4) = *reinterpret_cast<uint4*>(hi + q * 4);
        *reinterpret_cast<uint4*>(base + HW * 8 + q * 4) = *reinterpret_cast<uint4*>(lo + q * 4);
    }
}

// ===========================================================================
// prep_cam: camH = permuted fp16 copy of cam (GEMM3 A-operand)
// ===========================================================================
__global__ void __launch_bounds__(256)
prep_cam_kernel(const float* __restrict__ cam, __half* __restrict__ camH)
{
    const long i4 = (long)blockIdx.x * blockDim.x + threadIdx.x;
    const float4 v = reinterpret_cast<const float4*>(cam)[i4];
    const long row   = i4 >> 8;
    const int  idx4  = (int)(i4 & 255);
    const int  chunk = idx4 >> 2;
    const int  j     = idx4 & 3;
    const int slotA = ((2 * j) & 3) * 2 + ((2 * j) >> 2);
    const int slotB = ((2 * j + 1) & 3) * 2 + ((2 * j + 1) >> 2);
    __half2* base = reinterpret_cast<__half2*>(camH + row * HW + chunk * 16);
    base[slotA] = __floats2half2_rn(v.x, v.y);
    base[slotB] = __floats2half2_rn(v.z, v.w);
}

// ===========================================================================
// Softmax: fp32 row of 1024 -> fp16 permuted, in-place
// ===========================================================================
__global__ void __launch_bounds__(256)
softmax_kernel(float* __restrict__ P)
{
    __shared__ float red_m[8];
    __shared__ float red_s[8];

    const long row = blockIdx.x;
    float* rowp = P + row * (long)HW;
    const float4 v = reinterpret_cast<const float4*>(rowp)[threadIdx.x];

    const int lane = threadIdx.x & 31;
    const int warp = threadIdx.x >> 5;

    float m = fmaxf(fmaxf(v.x, v.y), fmaxf(v.z, v.w));
#pragma unroll
    for (int o = 16; o; o >>= 1) m = fmaxf(m, __shfl_xor_sync(0xffffffffu, m, o));
    if (lane == 0) red_m[warp] = m;
    __syncthreads();
    m = red_m[0];
#pragma unroll
    for (int i = 1; i < 8; i++) m = fmaxf(m, red_m[i]);

    float4 e;
    e.x = expf(v.x - m);
    e.y = expf(v.y - m);
    e.z = expf(v.z - m);
    e.w = expf(v.w - m);
    float s = e.x + e.y + e.z + e.w;
#pragma unroll
    for (int o = 16; o; o >>= 1) s += __shfl_xor_sync(0xffffffffu, s, o);
    if (lane == 0) red_s[warp] = s;
    __syncthreads();
    s = red_s[0];
#pragma unroll
    for (int i = 1; i < 8; i++) s += red_s[i];

    const float inv = 1.0f / s;
    const int chunk = threadIdx.x >> 2;
    const int j     = threadIdx.x & 3;
    const int slotA = ((2 * j) & 3) * 2 + ((2 * j) >> 2);
    const int slotB = ((2 * j + 1) & 3) * 2 + ((2 * j + 1) >> 2);
    __half2* base = reinterpret_cast<__half2*>(reinterpret_cast<__half*>(rowp) + chunk * 16);
    base[slotA] = __floats2half2_rn(e.x * inv, e.y * inv);
    base[slotB] = __floats2half2_rn(e.z * inv, e.w * inv);
}

// ===========================================================================
// Packed 3xbf16 GEMM (GEMM1 & GEMM2): C[b,m,n] = sum_k A(m,k) B(n,k)
//   Both operands in packed [chunk][hl][row][8] format (rows = m for A, n for B).
//   Mainloop: pure LDS.64 + HMMA, zero cvt.
// ===========================================================================
#define T2_BK 16
#define T2_STAGES 4
#define T2_STAGEU 4096                   // uint32 per stage (A 2048 + B 2048)
#define T2_SMEM_BYTES (T2_STAGES * T2_STAGEU * 4)   // 65536

__global__ void __launch_bounds__(256, 2)
pk_gemm_kernel(const uint32_t* __restrict__ Apk, const uint32_t* __restrict__ Bpk,
               float* __restrict__ Cg,
               int N, int kChunks,
               long bsA, long bsB, long bsC,
               int csA, int csB /* chunk strides (uint32); hl stride = cs/2 */)
{
    extern __shared__ uint32_t smu[];

    const int tid  = threadIdx.x;
    const int wid  = tid >> 5;
    const int lane = tid & 31;
    const int g    = lane >> 2;
    const int t    = lane & 3;
    const int wm   = wid >> 1;
    const int wn   = wid & 1;

    const int b  = blockIdx.z;
    const int m0 = blockIdx.y * 128;
    const int n0 = blockIdx.x * 128;
    const uint32_t* A = Apk + b * bsA;
    const uint32_t* B = Bpk + b * bsB;
    float* C = Cg + b * bsC;

    const uint32_t sm_u = smem_u32(smu);
    const int hsA = csA >> 1, hsB = csB >> 1;

    float acc[2][8][4];
#pragma unroll
    for (int i = 0; i < 2; i++)
#pragma unroll
        for (int j = 0; j < 8; j++)
#pragma unroll
            for (int k = 0; k < 4; k++) acc[i][j][k] = 0.f;

    auto load_stage = [&](int s, int c) {
        const uint32_t sa = sm_u + (uint32_t)(s * T2_STAGEU) * 4u;
        const uint32_t sb = sa + 2048 * 4u;
        // A: 2 hl x 128 rows x 32B = 512 x 16B
#pragma unroll
        for (int i = 0; i < 2; i++) {
            int cid = tid + i * 256;
            int hl = cid >> 8, rh = cid & 255;
            int row = rh >> 1, half = rh & 1;
            CP_ASYNC16(sa + (uint32_t)(hl * 1024 + row * 8 + half * 4) * 4u,
                       A + (long)c * csA + hl * hsA + (long)(m0 + row) * 8 + half * 4);
        }
#pragma unroll
        for (int i = 0; i < 2; i++) {
            int cid = tid + i * 256;
            int hl = cid >> 8, rh = cid & 255;
            int row = rh >> 1, half = rh & 1;
            CP_ASYNC16(sb + (uint32_t)(hl * 1024 + row * 8 + half * 4) * 4u,
                       B + (long)c * csB + hl * hsB + (long)(n0 + row) * 8 + half * 4);
        }
    };

#pragma unroll
    for (int s = 0; s < T2_STAGES - 1; s++) {
        load_stage(s, s);
        CP_COMMIT();
    }

    for (int it = 0; it < kChunks; it++) {
        CP_WAIT2();
        __syncthreads();

        const int s = it & (T2_STAGES - 1);
        const uint32_t* sa = smu + s * T2_STAGEU;
        const uint32_t* sb = sa + 2048;

        // A fragments: LDS.64 -> (low-k pair, high-k pair) per row
        uint32_t ahi[2][4], alo[2][4];
#pragma unroll
        for (int mt = 0; mt < 2; mt++) {
            const int r0 = wm * 32 + mt * 16 + g;
            const uint2 h0 = *reinterpret_cast<const uint2*>(sa + r0 * 8 + t * 2);
            const uint2 h1 = *reinterpret_cast<const uint2*>(sa + (r0 + 8) * 8 + t * 2);
            const uint2 l0 = *reinterpret_cast<const uint2*>(sa + 1024 + r0 * 8 + t * 2);
            const uint2 l1 = *reinterpret_cast<const uint2*>(sa + 1024 + (r0 + 8) * 8 + t * 2);
            ahi[mt][0] = h0.x; ahi[mt][1] = h1.x; ahi[mt][2] = h0.y; ahi[mt][3] = h1.y;
            alo[mt][0] = l0.x; alo[mt][1] = l1.x; alo[mt][2] = l0.y; alo[mt][3] = l1.y;
        }

#pragma unroll
        for (int nt = 0; nt < 8; nt++) {
            const int n = wn * 64 + nt * 8 + g;
            const uint2 bh = *reinterpret_cast<const uint2*>(sb + n * 8 + t * 2);
            const uint2 bl = *reinterpret_cast<const uint2*>(sb + 1024 + n * 8 + t * 2);
#pragma unroll
            for (int mt = 0; mt < 2; mt++) {
                mma_bf16(acc[mt][nt], ahi[mt], bh.x, bh.y);
                mma_bf16(acc[mt][nt], ahi[mt], bl.x, bl.y);
                mma_bf16(acc[mt][nt], alo[mt], bh.x, bh.y);
            }
        }

        __syncthreads();
        if (it + T2_STAGES - 1 < kChunks)
            load_stage((it + T2_STAGES - 1) & (T2_STAGES - 1), it + T2_STAGES - 1);
        CP_COMMIT();
    }

#pragma unroll
    for (int mt = 0; mt < 2; mt++) {
        const int mrow = m0 + wm * 32 + mt * 16 + g;
#pragma unroll
        for (int nt = 0; nt < 8; nt++) {
            const int n = n0 + wn * 64 + nt * 8 + 2 * t;
            *(float2*)(C + (long)mrow * N + n) = make_float2(acc[mt][nt][0], acc[mt][nt][1]);
            *(float2*)(C + (long)(mrow + 8) * N + n) = make_float2(acc[mt][nt][2], acc[mt][nt][3]);
        }
    }
}

// ===========================================================================
// GEMM3 (fp16 m16n8k16, pre-permuted operands) — unchanged
// ===========================================================================
#define G3_BM 128
#define G3_BN 128
#define G3_BK 32
#define G3_STAGES 4
#define G3_CHUNK_BYTES 4096
#define G3_TILE_BYTES  (2 * G3_CHUNK_BYTES)
#define G3_STAGE_BYTES (2 * G3_TILE_BYTES)
#define G3_SMEM_BYTES  (G3_STAGES * G3_STAGE_BYTES)
#define G3_KITER (HW / G3_BK)

__global__ void __launch_bounds__(256, 2)
gemm3_f16_kernel(const __half* __restrict__ camH, const float* __restrict__ cam,
                 const float* __restrict__ Pf,
                 float* __restrict__ out, const float* __restrict__ alphap)
{
    extern __shared__ char smc[];

    const int tid  = threadIdx.x;
    const int wid  = tid >> 5;
    const int lane = tid & 31;
    const int g    = lane >> 2;
    const int t    = lane & 3;
    const int wm   = wid >> 1;
    const int wn   = wid & 1;

    const int b  = blockIdx.z;
    const int m0 = blockIdx.y * G3_BM;
    const int n0 = blockIdx.x * G3_BN;
    const __half* camHB = camH + (long)b * CCH * HW;
    const float*  camB  = cam  + (long)b * CCH * HW;
    const __half* PBh = reinterpret_cast<const __half*>(Pf + (long)b * HW * HW);

    const uint32_t sm_u = smem_u32(smc);

    float acc[2][8][4];
#pragma unroll
    for (int i = 0; i < 2; i++)
#pragma unroll
        for (int j = 0; j < 8; j++)
#pragma unroll
            for (int k = 0; k < 4; k++) acc[i][j][k] = 0.f;

    auto load_stage = [&](int s, int k0) {
        const uint32_t sa = sm_u + (uint32_t)(s * G3_STAGE_BYTES);
        const uint32_t sb = sa + G3_TILE_BYTES;
#pragma unroll
        for (int i = 0; i < 2; i++) {
            int c = tid + i * 256;
            int row = c >> 2, q = c & 3;
            uint32_t dst = sa + (uint32_t)((q >> 1) * G3_CHUNK_BYTES + row * 32 + (q & 1) * 16);
            CP_ASYNC16(dst, camHB + (long)(m0 + row) * HW + k0 + q * 8);
        }
#pragma unroll
        for (int i = 0; i < 2; i++) {
            int c = tid + i * 256;
            int row = c >> 2, q = c & 3;
            uint32_t dst = sb + (uint32_t)((q >> 1) * G3_CHUNK_BYTES + row * 32 + (q & 1) * 16);
            CP_ASYNC16(dst, PBh + (long)(n0 + row) * 2048 + k0 + q * 8);
        }
    };

#pragma unroll
    for (int s = 0; s < G3_STAGES - 1; s++) {
        load_stage(s, s * G3_BK);
        CP_COMMIT();
    }

    for (int it = 0; it < G3_KITER; it++) {
        CP_WAIT2();
        __syncthreads();

        const int s = it & (G3_STAGES - 1);
        const char* sa = smc + s * G3_STAGE_BYTES;
        const char* sb = sa + G3_TILE_BYTES;

#pragma unroll
        for (int ch = 0; ch < 2; ch++) {
            const char* sac = sa + ch * G3_CHUNK_BYTES;
            const char* sbc = sb + ch * G3_CHUNK_BYTES;

            uint2 af[2][2];
#pragma unroll
            for (int mt = 0; mt < 2; mt++) {
                const int r0 = wm * 32 + mt * 16 + g;
                af[mt][0] = *reinterpret_cast<const uint2*>(sac + r0 * 32 + t * 8);
                af[mt][1] = *reinterpret_cast<const uint2*>(sac + (r0 + 8) * 32 + t * 8);
            }
            uint2 bf[8];
#pragma unroll
            for (int nt = 0; nt < 8; nt++) {
                const int n = wn * 64 + nt * 8 + g;
                bf[nt] = *reinterpret_cast<const uint2*>(sbc + n * 32 + t * 8);
            }
#pragma unroll
            for (int mt = 0; mt < 2; mt++)
#pragma unroll
                for (int nt = 0; nt < 8; nt++)
                    mma_f16(acc[mt][nt], af[mt][0].x, af[mt][1].x, af[mt][0].y, af[mt][1].y,
                            bf[nt].x, bf[nt].y);
        }

        __syncthreads();
        if (it + G3_STAGES - 1 < G3_KITER)
            load_stage((it + G3_STAGES - 1) & (G3_STAGES - 1), (it + G3_STAGES - 1) * G3_BK);
        CP_COMMIT();
    }

    const float alpha = *alphap;
    float* outB = out + (long)b * CCH * HW;
#pragma unroll
    for (int mt = 0; mt < 2; mt++) {
        const int mrow = m0 + wm * 32 + mt * 16 + g;
#pragma unroll
        for (int nt = 0; nt < 8; nt++) {
            const int n = n0 + wn * 64 + nt * 8 + 2 * t;
            {
                const float2 cv = *(const float2*)(camB + (long)mrow * HW + n);
                float2 o;
                o.x = alpha * acc[mt][nt][0] + cv.x;
                o.y = alpha * acc[mt][nt][1] + cv.y;
                *(float2*)(outB + (long)mrow * HW + n) = o;
            }
            {
                const float2 cv = *(const float2*)(camB + (long)(mrow + 8) * HW + n);
                float2 o;
                o.x = alpha * acc[mt][nt][2] + cv.x;
                o.y = alpha * acc[mt][nt][3] + cv.y;
                *(float2*)(outB + (long)(mrow + 8) * HW + n) = o;
            }
        }
    }
}

// ---------------------------------------------------------------------------
extern "C" void kernel_launch(void* const* d_in, const int* in_sizes, int n_in,
                              void* d_out, int out_size)
{
    const float* feat  = (const float*)d_in[0];
    const float* cam   = (const float*)d_in[1];
    const float* Wq    = (const float*)d_in[2];
    const float* Wk    = (const float*)d_in[3];
    const float* alpha = (const float*)d_in[4];
    float* out = (float*)d_out;

    float *f12, *P;
    __half* camH;
    uint32_t *Wpk, *featPk, *f12pk;
    cudaGetSymbolAddress((void**)&f12, g_f12);
    cudaGetSymbolAddress((void**)&P, g_P);
    cudaGetSymbolAddress((void**)&camH, g_camH);
    cudaGetSymbolAddress((void**)&Wpk, g_Wpk);
    cudaGetSymbolAddress((void**)&featPk, g_featPk);
    cudaGetSymbolAddress((void**)&f12pk, g_f12pk);

    // Preps (independent)
    prep_w_kernel<<<128, 256>>>(Wq, Wk, Wpk);
    pack_rows_kernel<<<(unsigned)((long)BATCH * 128 * HW / 256), 256>>>(feat, featPk, 128);
    prep_cam_kernel<<<(unsigned)((long)BATCH * CCH * HW / 4 / 256), 256>>>(cam, camH);

    cudaFuncSetAttribute(pk_gemm_kernel, cudaFuncAttributeMaxDynamicSharedMemorySize, T2_SMEM_BYTES);

    // GEMM1: f12[b,m,n] = W[m,k] feat[b,k,n]   (M=256, N=1024, K=2048 -> 128 chunks)
    {
        dim3 grid(HW / 128, 256 / 128, BATCH);
        pk_gemm_kernel<<<grid, 256, T2_SMEM_BYTES>>>(
            Wpk, featPk, f12,
            HW, 128,
            0L, (long)128 * 2 * HW * 8, (long)256 * HW,
            2 * 256 * 8, 2 * HW * 8);
    }

    // repack f12 -> packed (pairs across mid dim; 256 mids -> 16 chunks)
    pack_rows_kernel<<<(unsigned)((long)BATCH * 16 * HW / 256), 256>>>(f12, f12pk, 16);

    // GEMM2: S[b,i,j] = sum_m f1[b,m,i] f2[b,m,j]  (A = chunks 0..7, B = chunks 8..15)
    {
        dim3 grid(HW / 128, HW / 128, BATCH);
        pk_gemm_kernel<<<grid, 256, T2_SMEM_BYTES>>>(
            f12pk, f12pk + (long)8 * 2 * HW * 8, P,
            HW, 8,
            (long)16 * 2 * HW * 8, (long)16 * 2 * HW * 8, (long)HW * HW,
            2 * HW * 8, 2 * HW * 8);
    }

    // Softmax (fp32 -> permuted fp16, in-place)
    softmax_kernel<<<BATCH * HW, 256>>>(P);

    // GEMM3 (fp16 m16n8k16): out = alpha * cam @ P^T + cam
    {
        cudaFuncSetAttribute(gemm3_f16_kernel,
                             cudaFuncAttributeMaxDynamicSharedMemorySize, G3_SMEM_BYTES);
        dim3 grid(HW / G3_BN, CCH / G3_BM, BATCH);
        gemm3_f16_kernel<<<grid, 256, G3_SMEM_BYTES>>>(camH, cam, P, out, alpha);
    }
}

// round 8
// speedup vs baseline: 3.5410x; 1.0306x over previous
#include <cuda_runtime.h>
#include <cuda_fp16.h>
#include <cstdint>

// Problem constants
#define BATCH 32
#define CCH   2048
#define HW    1024
#define MID   128

// Scratch (allocation-free rule: __device__ globals)
static __device__ float    g_f12[(long)BATCH * 2 * MID * HW];          // 32 MB fp32 (GEMM1 out)
static __device__ float    g_P[(long)BATCH * HW * HW];                 // 128 MB
static __device__ __half   g_camH[(long)BATCH * CCH * HW];             // 128 MB
static __device__ uint32_t g_Wpk[128 * 4096];                          // 2 MB
static __device__ uint32_t g_featPk[(long)BATCH * 128 * 2 * HW * 8];   // 256 MB
static __device__ uint32_t g_f12pk[(long)BATCH * 16 * 2 * HW * 8];     // 32 MB

// ===========================================================================
// Helpers
// ===========================================================================
__device__ __forceinline__ uint32_t smem_u32(const void* p) {
    uint32_t a;
    asm("{ .reg .u64 t; cvta.to.shared.u64 t, %1; cvt.u32.u64 %0, t; }" : "=r"(a) : "l"(p));
    return a;
}
__device__ __forceinline__ void mma_f16(float* c, uint32_t a0, uint32_t a1, uint32_t a2, uint32_t a3,
                                        uint32_t b0, uint32_t b1) {
    asm volatile(
        "mma.sync.aligned.m16n8k16.row.col.f32.f16.f16.f32 "
        "{%0,%1,%2,%3}, {%4,%5,%6,%7}, {%8,%9}, {%0,%1,%2,%3};"
        : "+f"(c[0]), "+f"(c[1]), "+f"(c[2]), "+f"(c[3])
        : "r"(a0), "r"(a1), "r"(a2), "r"(a3), "r"(b0), "r"(b1));
}
__device__ __forceinline__ void mma_bf16(float* c, const uint32_t* a, uint32_t b0, uint32_t b1) {
    asm volatile(
        "mma.sync.aligned.m16n8k16.row.col.f32.bf16.bf16.f32 "
        "{%0,%1,%2,%3}, {%4,%5,%6,%7}, {%8,%9}, {%0,%1,%2,%3};"
        : "+f"(c[0]), "+f"(c[1]), "+f"(c[2]), "+f"(c[3])
        : "r"(a[0]), "r"(a[1]), "r"(a[2]), "r"(a[3]), "r"(b0), "r"(b1));
}
__device__ __forceinline__ uint32_t bf16x2_pack(float e, float o) {
    uint32_t r;
    asm("cvt.rn.bf16x2.f32 %0, %1, %2;" : "=r"(r) : "f"(o), "f"(e));
    return r;
}
__device__ __forceinline__ uint32_t bf16x2_residual(float e, float o, uint32_t hi) {
    const float he = __uint_as_float(hi << 16);
    const float ho = __uint_as_float(hi & 0xffff0000u);
    return bf16x2_pack(e - he, o - ho);
}
#define CP_ASYNC16(smem_addr, gptr) \
    asm volatile("cp.async.cg.shared.global [%0], [%1], 16;" :: "r"(smem_addr), "l"(gptr))
#define CP_COMMIT() asm volatile("cp.async.commit_group;" ::: "memory")
#define CP_WAIT2()  asm volatile("cp.async.wait_group 2;"  ::: "memory")

// ===========================================================================
// prep_w: Wq/Wk [128][2048] -> packed [128 chunks][hl][256 rows][8]
// ===========================================================================
__global__ void __launch_bounds__(256)
prep_w_kernel(const float* __restrict__ Wq, const float* __restrict__ Wk,
              uint32_t* __restrict__ Wpk)
{
    const int idx = blockIdx.x * 256 + threadIdx.x;
    const int m = idx >> 7;
    const int c = idx & 127;
    const float* src = (m < 128 ? Wq + (long)m * CCH : Wk + (long)(m - 128) * CCH) + c * 16;

    float f[16];
#pragma unroll
    for (int q = 0; q < 4; q++)
        *reinterpret_cast<float4*>(f + q * 4) = *reinterpret_cast<const float4*>(src + q * 4);

    uint32_t hi[8], lo[8];
#pragma unroll
    for (int u = 0; u < 8; u++) {
        const int p = (u < 4) ? 2 * u : 2 * u - 7;
        hi[p] = bf16x2_pack(f[2 * u], f[2 * u + 1]);
        lo[p] = bf16x2_residual(f[2 * u], f[2 * u + 1], hi[p]);
    }
    uint32_t* dhi = Wpk + (long)c * 4096 + m * 8;
    uint32_t* dlo = dhi + 2048;
#pragma unroll
    for (int q = 0; q < 8; q++) { dhi[q] = hi[q]; dlo[q] = lo[q]; }
}

// ===========================================================================
// pack_rows: [C][n] fp32 -> packed (pairs across first dim)
// ===========================================================================
__global__ void __launch_bounds__(256)
pack_rows_kernel(const float* __restrict__ src, uint32_t* __restrict__ dst,
                 int chunks)
{
    const long idx = (long)blockIdx.x * 256 + threadIdx.x;
    const int  n   = (int)(idx & (HW - 1));
    const long bc  = idx >> 10;
    const int  c   = (int)(bc % chunks);
    const long b   = bc / chunks;

    const float* s = src + (b * chunks + c) * 16 * (long)HW + n;
    float f[16];
#pragma unroll
    for (int j = 0; j < 16; j++) f[j] = s[(long)j * HW];

    uint32_t hi[8], lo[8];
#pragma unroll
    for (int u = 0; u < 8; u++) {
        const int p = (u < 4) ? 2 * u : 2 * u - 7;
        hi[p] = bf16x2_pack(f[2 * u], f[2 * u + 1]);
        lo[p] = bf16x2_residual(f[2 * u], f[2 * u + 1], hi[p]);
    }
    uint32_t* base = dst + (b * chunks + c) * (long)(2 * HW * 8) + n * 8;
#pragma unroll
    for (int q = 0; q < 2; q++) {
        *reinterpret_cast<uint4*>(base + q * 4) = *reinterpret_cast<uint4*>(hi + q * 4);
        *reinterpret_cast<uint4*>(base + HW * 8 + q * 4) = *reinterpret_cast<uint4*>(lo + q * 4);
    }
}

// ===========================================================================
// prep_cam: camH = permuted fp16 copy of cam (GEMM3 A-operand)
// ===========================================================================
__global__ void __launch_bounds__(256)
prep_cam_kernel(const float* __restrict__ cam, __half* __restrict__ camH)
{
    const long i4 = (long)blockIdx.x * blockDim.x + threadIdx.x;
    const float4 v = reinterpret_cast<const float4*>(cam)[i4];
    const long row   = i4 >> 8;
    const int  idx4  = (int)(i4 & 255);
    const int  chunk = idx4 >> 2;
    const int  j     = idx4 & 3;
    const int slotA = ((2 * j) & 3) * 2 + ((2 * j) >> 2);
    const int slotB = ((2 * j + 1) & 3) * 2 + ((2 * j + 1) >> 2);
    __half2* base = reinterpret_cast<__half2*>(camH + row * HW + chunk * 16);
    base[slotA] = __floats2half2_rn(v.x, v.y);
    base[slotB] = __floats2half2_rn(v.z, v.w);
}

// ===========================================================================
// Softmax: fp32 row of 1024 -> fp16 permuted, in-place
// ===========================================================================
__global__ void __launch_bounds__(256)
softmax_kernel(float* __restrict__ P)
{
    __shared__ float red_m[8];
    __shared__ float red_s[8];

    const long row = blockIdx.x;
    float* rowp = P + row * (long)HW;
    const float4 v = reinterpret_cast<const float4*>(rowp)[threadIdx.x];

    const int lane = threadIdx.x & 31;
    const int warp = threadIdx.x >> 5;

    float m = fmaxf(fmaxf(v.x, v.y), fmaxf(v.z, v.w));
#pragma unroll
    for (int o = 16; o; o >>= 1) m = fmaxf(m, __shfl_xor_sync(0xffffffffu, m, o));
    if (lane == 0) red_m[warp] = m;
    __syncthreads();
    m = red_m[0];
#pragma unroll
    for (int i = 1; i < 8; i++) m = fmaxf(m, red_m[i]);

    float4 e;
    e.x = expf(v.x - m);
    e.y = expf(v.y - m);
    e.z = expf(v.z - m);
    e.w = expf(v.w - m);
    float s = e.x + e.y + e.z + e.w;
#pragma unroll
    for (int o = 16; o; o >>= 1) s += __shfl_xor_sync(0xffffffffu, s, o);
    if (lane == 0) red_s[warp] = s;
    __syncthreads();
    s = red_s[0];
#pragma unroll
    for (int i = 1; i < 8; i++) s += red_s[i];

    const float inv = 1.0f / s;
    const int chunk = threadIdx.x >> 2;
    const int j     = threadIdx.x & 3;
    const int slotA = ((2 * j) & 3) * 2 + ((2 * j) >> 2);
    const int slotB = ((2 * j + 1) & 3) * 2 + ((2 * j + 1) >> 2);
    __half2* base = reinterpret_cast<__half2*>(reinterpret_cast<__half*>(rowp) + chunk * 16);
    base[slotA] = __floats2half2_rn(e.x * inv, e.y * inv);
    base[slotB] = __floats2half2_rn(e.z * inv, e.w * inv);
}

// ===========================================================================
// Packed 3xbf16 GEMM (GEMM1 & GEMM2), single-barrier pipeline, compile-time
// strides, running global pointers.
// ===========================================================================
#define T2_STAGES 4
#define T2_STAGEU 4096
#define T2_SMEM_BYTES (T2_STAGES * T2_STAGEU * 4)   // 65536

template<int KCHUNKS, int CSA, int CSB>
__global__ void __launch_bounds__(256, 2)
pk_gemm_kernel(const uint32_t* __restrict__ Apk, const uint32_t* __restrict__ Bpk,
               float* __restrict__ Cg,
               long bsA, long bsB, long bsC)
{
    extern __shared__ uint32_t smu[];

    const int tid  = threadIdx.x;
    const int wid  = tid >> 5;
    const int lane = tid & 31;
    const int g    = lane >> 2;
    const int t    = lane & 3;
    const int wm   = wid >> 1;
    const int wn   = wid & 1;

    const int b  = blockIdx.z;
    const int m0 = blockIdx.y * 128;
    const int n0 = blockIdx.x * 128;
    float* C = Cg + b * bsC;

    const uint32_t sm_u = smem_u32(smu);

    // Hoisted per-thread load descriptors (2 chunks of 16B for A, 2 for B)
    uint32_t sOffA[2], sOffB[2];
    const uint32_t* aPtr[2];
    const uint32_t* bPtr[2];
#pragma unroll
    for (int i = 0; i < 2; i++) {
        const int cid = tid + i * 256;
        const int hl = cid >> 8, rh = cid & 255;
        const int row = rh >> 1, half = rh & 1;
        sOffA[i] = (uint32_t)(hl * 1024 + row * 8 + half * 4) * 4u;
        sOffB[i] = sOffA[i] + 2048u * 4u;
        aPtr[i] = Apk + b * bsA + hl * (CSA / 2) + (long)(m0 + row) * 8 + half * 4;
        bPtr[i] = Bpk + b * bsB + hl * (CSB / 2) + (long)(n0 + row) * 8 + half * 4;
    }

    float acc[2][8][4];
#pragma unroll
    for (int i = 0; i < 2; i++)
#pragma unroll
        for (int j = 0; j < 8; j++)
#pragma unroll
            for (int k = 0; k < 4; k++) acc[i][j][k] = 0.f;

    auto load_stage = [&](int s) {
        const uint32_t sa = sm_u + (uint32_t)(s * T2_STAGEU) * 4u;
#pragma unroll
        for (int i = 0; i < 2; i++) {
            CP_ASYNC16(sa + sOffA[i], aPtr[i]);
            aPtr[i] += CSA;
        }
#pragma unroll
        for (int i = 0; i < 2; i++) {
            CP_ASYNC16(sa + sOffB[i], bPtr[i]);
            bPtr[i] += CSB;
        }
    };

#pragma unroll
    for (int s = 0; s < T2_STAGES - 1; s++) {
        load_stage(s);
        CP_COMMIT();
    }

    for (int it = 0; it < KCHUNKS; it++) {
        CP_WAIT2();
        __syncthreads();
        if (it + T2_STAGES - 1 < KCHUNKS)
            load_stage((it + T2_STAGES - 1) & (T2_STAGES - 1));
        CP_COMMIT();

        const int s = it & (T2_STAGES - 1);
        const uint32_t* sa = smu + s * T2_STAGEU;
        const uint32_t* sb = sa + 2048;

        uint32_t ahi[2][4], alo[2][4];
#pragma unroll
        for (int mt = 0; mt < 2; mt++) {
            const int r0 = wm * 32 + mt * 16 + g;
            const uint2 h0 = *reinterpret_cast<const uint2*>(sa + r0 * 8 + t * 2);
            const uint2 h1 = *reinterpret_cast<const uint2*>(sa + (r0 + 8) * 8 + t * 2);
            const uint2 l0 = *reinterpret_cast<const uint2*>(sa + 1024 + r0 * 8 + t * 2);
            const uint2 l1 = *reinterpret_cast<const uint2*>(sa + 1024 + (r0 + 8) * 8 + t * 2);
            ahi[mt][0] = h0.x; ahi[mt][1] = h1.x; ahi[mt][2] = h0.y; ahi[mt][3] = h1.y;
            alo[mt][0] = l0.x; alo[mt][1] = l1.x; alo[mt][2] = l0.y; alo[mt][3] = l1.y;
        }

#pragma unroll
        for (int nt = 0; nt < 8; nt++) {
            const int n = wn * 64 + nt * 8 + g;
            const uint2 bh = *reinterpret_cast<const uint2*>(sb + n * 8 + t * 2);
            const uint2 bl = *reinterpret_cast<const uint2*>(sb + 1024 + n * 8 + t * 2);
#pragma unroll
            for (int mt = 0; mt < 2; mt++) {
                mma_bf16(acc[mt][nt], ahi[mt], bh.x, bh.y);
                mma_bf16(acc[mt][nt], ahi[mt], bl.x, bl.y);
                mma_bf16(acc[mt][nt], alo[mt], bh.x, bh.y);
            }
        }
        __syncthreads();
    }

#pragma unroll
    for (int mt = 0; mt < 2; mt++) {
        const int mrow = m0 + wm * 32 + mt * 16 + g;
#pragma unroll
        for (int nt = 0; nt < 8; nt++) {
            const int n = n0 + wn * 64 + nt * 8 + 2 * t;
            *(float2*)(C + (long)mrow * HW + n) = make_float2(acc[mt][nt][0], acc[mt][nt][1]);
            *(float2*)(C + (long)(mrow + 8) * HW + n) = make_float2(acc[mt][nt][2], acc[mt][nt][3]);
        }
    }
}

// ===========================================================================
// GEMM3 (fp16 m16n8k16), single-barrier pipeline, running pointers
// ===========================================================================
#define G3_BM 128
#define G3_BN 128
#define G3_BK 32
#define G3_STAGES 4
#define G3_CHUNK_BYTES 4096
#define G3_TILE_BYTES  (2 * G3_CHUNK_BYTES)
#define G3_STAGE_BYTES (2 * G3_TILE_BYTES)
#define G3_SMEM_BYTES  (G3_STAGES * G3_STAGE_BYTES)
#define G3_KITER (HW / G3_BK)

__global__ void __launch_bounds__(256, 2)
gemm3_f16_kernel(const __half* __restrict__ camH, const float* __restrict__ cam,
                 const float* __restrict__ Pf,
                 float* __restrict__ out, const float* __restrict__ alphap)
{
    extern __shared__ char smc[];

    const int tid  = threadIdx.x;
    const int wid  = tid >> 5;
    const int lane = tid & 31;
    const int g    = lane >> 2;
    const int t    = lane & 3;
    const int wm   = wid >> 1;
    const int wn   = wid & 1;

    const int b  = blockIdx.z;
    const int m0 = blockIdx.y * G3_BM;
    const int n0 = blockIdx.x * G3_BN;
    const float* camB = cam + (long)b * CCH * HW;

    const uint32_t sm_u = smem_u32(smc);

    // Hoisted load descriptors
    uint32_t sOff[2];
    const __half* aPtr[2];
    const __half* bPtr[2];
    {
        const __half* camHB = camH + (long)b * CCH * HW;
        const __half* PBh = reinterpret_cast<const __half*>(Pf + (long)b * HW * HW);
#pragma unroll
        for (int i = 0; i < 2; i++) {
            const int c = tid + i * 256;
            const int row = c >> 2, q = c & 3;
            sOff[i] = (uint32_t)((q >> 1) * G3_CHUNK_BYTES + row * 32 + (q & 1) * 16);
            aPtr[i] = camHB + (long)(m0 + row) * HW + q * 8;
            bPtr[i] = PBh + (long)(n0 + row) * 2048 + q * 8;
        }
    }

    float acc[2][8][4];
#pragma unroll
    for (int i = 0; i < 2; i++)
#pragma unroll
        for (int j = 0; j < 8; j++)
#pragma unroll
            for (int k = 0; k < 4; k++) acc[i][j][k] = 0.f;

    auto load_stage = [&](int s) {
        const uint32_t sa = sm_u + (uint32_t)(s * G3_STAGE_BYTES);
        const uint32_t sb = sa + G3_TILE_BYTES;
#pragma unroll
        for (int i = 0; i < 2; i++) {
            CP_ASYNC16(sa + sOff[i], aPtr[i]);
            aPtr[i] += G3_BK;
        }
#pragma unroll
        for (int i = 0; i < 2; i++) {
            CP_ASYNC16(sb + sOff[i], bPtr[i]);
            bPtr[i] += G3_BK;
        }
    };

#pragma unroll
    for (int s = 0; s < G3_STAGES - 1; s++) {
        load_stage(s);
        CP_COMMIT();
    }

    for (int it = 0; it < G3_KITER; it++) {
        CP_WAIT2();
        __syncthreads();
        if (it + G3_STAGES - 1 < G3_KITER)
            load_stage((it + G3_STAGES - 1) & (G3_STAGES - 1));
        CP_COMMIT();

        const int s = it & (G3_STAGES - 1);
        const char* sa = smc + s * G3_STAGE_BYTES;
        const char* sb = sa + G3_TILE_BYTES;

#pragma unroll
        for (int ch = 0; ch < 2; ch++) {
            const char* sac = sa + ch * G3_CHUNK_BYTES;
            const char* sbc = sb + ch * G3_CHUNK_BYTES;

            uint2 af[2][2];
#pragma unroll
            for (int mt = 0; mt < 2; mt++) {
                const int r0 = wm * 32 + mt * 16 + g;
                af[mt][0] = *reinterpret_cast<const uint2*>(sac + r0 * 32 + t * 8);
                af[mt][1] = *reinterpret_cast<const uint2*>(sac + (r0 + 8) * 32 + t * 8);
            }
            uint2 bf[8];
#pragma unroll
            for (int nt = 0; nt < 8; nt++) {
                const int n = wn * 64 + nt * 8 + g;
                bf[nt] = *reinterpret_cast<const uint2*>(sbc + n * 32 + t * 8);
            }
#pragma unroll
            for (int mt = 0; mt < 2; mt++)
#pragma unroll
                for (int nt = 0; nt < 8; nt++)
                    mma_f16(acc[mt][nt], af[mt][0].x, af[mt][1].x, af[mt][0].y, af[mt][1].y,
                            bf[nt].x, bf[nt].y);
        }
        __syncthreads();
    }

    const float alpha = *alphap;
    float* outB = out + (long)b * CCH * HW;
#pragma unroll
    for (int mt = 0; mt < 2; mt++) {
        const int mrow = m0 + wm * 32 + mt * 16 + g;
#pragma unroll
        for (int nt = 0; nt < 8; nt++) {
            const int n = n0 + wn * 64 + nt * 8 + 2 * t;
            {
                const float2 cv = *(const float2*)(camB + (long)mrow * HW + n);
                float2 o;
                o.x = alpha * acc[mt][nt][0] + cv.x;
                o.y = alpha * acc[mt][nt][1] + cv.y;
                *(float2*)(outB + (long)mrow * HW + n) = o;
            }
            {
                const float2 cv = *(const float2*)(camB + (long)(mrow + 8) * HW + n);
                float2 o;
                o.x = alpha * acc[mt][nt][2] + cv.x;
                o.y = alpha * acc[mt][nt][3] + cv.y;
                *(float2*)(outB + (long)(mrow + 8) * HW + n) = o;
            }
        }
    }
}

// ---------------------------------------------------------------------------
extern "C" void kernel_launch(void* const* d_in, const int* in_sizes, int n_in,
                              void* d_out, int out_size)
{
    const float* feat  = (const float*)d_in[0];
    const float* cam   = (const float*)d_in[1];
    const float* Wq    = (const float*)d_in[2];
    const float* Wk    = (const float*)d_in[3];
    const float* alpha = (const float*)d_in[4];
    float* out = (float*)d_out;

    float *f12, *P;
    __half* camH;
    uint32_t *Wpk, *featPk, *f12pk;
    cudaGetSymbolAddress((void**)&f12, g_f12);
    cudaGetSymbolAddress((void**)&P, g_P);
    cudaGetSymbolAddress((void**)&camH, g_camH);
    cudaGetSymbolAddress((void**)&Wpk, g_Wpk);
    cudaGetSymbolAddress((void**)&featPk, g_featPk);
    cudaGetSymbolAddress((void**)&f12pk, g_f12pk);

    // Preps (independent)
    prep_w_kernel<<<128, 256>>>(Wq, Wk, Wpk);
    pack_rows_kernel<<<(unsigned)((long)BATCH * 128 * HW / 256), 256>>>(feat, featPk, 128);
    prep_cam_kernel<<<(unsigned)((long)BATCH * CCH * HW / 4 / 256), 256>>>(cam, camH);

    // GEMM1: f12[b,m,n] = W[m,k] feat[b,k,n]   (128 chunks; CSA=4096, CSB=16384)
    {
        cudaFuncSetAttribute((const void*)pk_gemm_kernel<128, 4096, 16384>,
                             cudaFuncAttributeMaxDynamicSharedMemorySize, T2_SMEM_BYTES);
        dim3 grid(HW / 128, 256 / 128, BATCH);
        pk_gemm_kernel<128, 4096, 16384><<<grid, 256, T2_SMEM_BYTES>>>(
            Wpk, featPk, f12,
            0L, (long)128 * 2 * HW * 8, (long)256 * HW);
    }

    // repack f12 -> packed (256 mids -> 16 chunks)
    pack_rows_kernel<<<(unsigned)((long)BATCH * 16 * HW / 256), 256>>>(f12, f12pk, 16);

    // GEMM2: S[b,i,j] = sum_m f1[b,m,i] f2[b,m,j]  (8 chunks; CSA=CSB=16384)
    {
        cudaFuncSetAttribute((const void*)pk_gemm_kernel<8, 16384, 16384>,
                             cudaFuncAttributeMaxDynamicSharedMemorySize, T2_SMEM_BYTES);
        dim3 grid(HW / 128, HW / 128, BATCH);
        pk_gemm_kernel<8, 16384, 16384><<<grid, 256, T2_SMEM_BYTES>>>(
            f12pk, f12pk + (long)8 * 2 * HW * 8, P,
            (long)16 * 2 * HW * 8, (long)16 * 2 * HW * 8, (long)HW * HW);
    }

    // Softmax (fp32 -> permuted fp16, in-place)
    softmax_kernel<<<BATCH * HW, 256>>>(P);

    // GEMM3 (fp16 m16n8k16): out = alpha * cam @ P^T + cam
    {
        cudaFuncSetAttribute(gemm3_f16_kernel,
                             cudaFuncAttributeMaxDynamicSharedMemorySize, G3_SMEM_BYTES);
        dim3 grid(HW / G3_BN, CCH / G3_BM, BATCH);
        gemm3_f16_kernel<<<grid, 256, G3_SMEM_BYTES>>>(camH, cam, P, out, alpha);
    }
}